// round 14
// baseline (speedup 1.0000x reference)
#include <cuda_runtime.h>
#include <cuda_bf16.h>
#include <math.h>
#include <stdint.h>
#include <stddef.h>

typedef unsigned long long u64;

// Problem dims
#define BB    64
#define TT    512
#define EE    768
#define HH    512
#define G3    1536
#define NF    256
#define MALL  (BB*TT)          // 32768

#define NBLK      128

// -------- mma recurrence config (2-plane, layers) --------
#define SWS     520
#define MSM_W   0
#define MSM_WL  (48*SWS)
#define MSM_HH  (96*SWS)
#define MSM_HL  (112*SWS)
#define MSM_BF  (128*SWS)
#define MRED_STR 52
#define MSM_BYTES (MSM_BF*2 + 4*16*MRED_STR*4)   // 146432 B

// -------- mma recurrence config (3-plane, selector) --------
#define M3_W1  0
#define M3_W2  (48*SWS)
#define M3_W3  (96*SWS)
#define M3_H1  (144*SWS)
#define M3_H2  (160*SWS)
#define M3_H3  (176*SWS)
#define M3_BF  (192*SWS)
#define M3_BYTES (M3_BF*2 + 4*16*MRED_STR*4)     // 212992 B

// -------- bf16 tensor GEMM config --------
#define SAS   40
#define OPSZ  (128*SAS*2)
#define BSM_BYTES  (8*OPSZ)          // 2-plane: 2 bufs x 4 planes = 81920 B
#define BSM3_BYTES (12*OPSZ)         // 3-plane: 2 bufs x 6 planes = 122880 B

// ----------------- device scratch (statics; no cudaMalloc allowed) ----------
__device__ float g_Gi[(size_t)MALL * G3];
__device__ float g_seq0[(size_t)MALL * HH];    // selector hist (fp32, argmax)
__device__ float g_U[(size_t)MALL * (NF*5)];
__device__ float g_h[2][BB * HH];
__device__ int   g_sel[BB * TT];
__device__ int   g_order[BB * TT];
__device__ int   g_nsel[BB];
__device__ float g_pooled[BB * 3 * NF];
__device__ unsigned g_bar4[4 * 32];
// bf16 split buffers (3rd plane used by selector path only)
__device__ __nv_bfloat16 g_Ah[(size_t)MALL * EE];
__device__ __nv_bfloat16 g_Al[(size_t)MALL * EE];
__device__ __nv_bfloat16 g_A3[(size_t)MALL * EE];
__device__ __nv_bfloat16 g_Wh[G3 * EE];
__device__ __nv_bfloat16 g_Wl[G3 * EE];
__device__ __nv_bfloat16 g_W3[G3 * EE];

// ----------------------------- sync helpers ---------------------------------
__device__ __forceinline__ unsigned ld_acq(const unsigned* p) {
    unsigned v;
    asm volatile("ld.acquire.gpu.global.u32 %0,[%1];" : "=r"(v) : "l"(p));
    return v;
}
__device__ __forceinline__ void red_rel(unsigned* p) {
    asm volatile("red.release.gpu.global.add.u32 [%0],1;" :: "l"(p));
}
// ----------------------------- mma helpers ----------------------------------
__device__ __forceinline__ void ldm4(unsigned* r, unsigned addr) {
    asm volatile("ldmatrix.sync.aligned.m8n8.x4.shared.b16 {%0,%1,%2,%3}, [%4];"
                 : "=r"(r[0]), "=r"(r[1]), "=r"(r[2]), "=r"(r[3]) : "r"(addr));
}
__device__ __forceinline__ void mma16816(float* c, const unsigned* a,
                                         unsigned b0, unsigned b1) {
    asm volatile("mma.sync.aligned.m16n8k16.row.col.f32.bf16.bf16.f32 "
                 "{%0,%1,%2,%3}, {%4,%5,%6,%7}, {%8,%9}, {%0,%1,%2,%3};"
                 : "+f"(c[0]), "+f"(c[1]), "+f"(c[2]), "+f"(c[3])
                 : "r"(a[0]), "r"(a[1]), "r"(a[2]), "r"(a[3]), "r"(b0), "r"(b1));
}

// ---------------------------------------------------------------------------
__global__ void k_reset() {
    int i = blockIdx.x * blockDim.x + threadIdx.x;
    if (i < 4 * 32) g_bar4[i] = 0u;
    if (i < 2 * BB * HH) ((float*)g_h)[i] = 0.f;
}
__global__ void k_zero_pooled() {
    int i = blockIdx.x * blockDim.x + threadIdx.x;
    if (i < BB * 3 * NF) g_pooled[i] = 0.f;
}
// split fp32 -> 2 bf16 planes
__global__ void k_split(const float* __restrict__ src,
                        __nv_bfloat16* __restrict__ p1,
                        __nv_bfloat16* __restrict__ p2, size_t n) {
    size_t i = (size_t)blockIdx.x * blockDim.x + threadIdx.x;
    if (i >= n) return;
    float x = src[i];
    __nv_bfloat16 h = __float2bfloat16(x);
    p1[i] = h;
    p2[i] = __float2bfloat16(x - __bfloat162float(h));
}
// split fp32 -> 3 bf16 planes (residual chain; combined error ~2^-24)
__global__ void k_split3(const float* __restrict__ src,
                         __nv_bfloat16* __restrict__ p1,
                         __nv_bfloat16* __restrict__ p2,
                         __nv_bfloat16* __restrict__ p3, size_t n) {
    size_t i = (size_t)blockIdx.x * blockDim.x + threadIdx.x;
    if (i >= n) return;
    float x = src[i];
    __nv_bfloat16 h1 = __float2bfloat16(x);
    float r = x - __bfloat162float(h1);
    __nv_bfloat16 h2 = __float2bfloat16(r);
    float r2 = r - __bfloat162float(h2);
    p1[i] = h1;
    p2[i] = h2;
    p3[i] = __float2bfloat16(r2);
}

// ---------------------------------------------------------------------------
// split-bf16 tensor-core GEMM, 2-plane / 3-term (layers + convs)
// mode 0 compute; mode 1 skip all-invalid 128-row tiles (no write).
// launch_bounds(256,2): cap regs at 128 so 2 CTAs/SM co-reside (163KB smem).
// ---------------------------------------------------------------------------
__global__ __launch_bounds__(256, 2)
void k_bgemm(float* __restrict__ C,
             const __nv_bfloat16* __restrict__ Ah, const __nv_bfloat16* __restrict__ Al,
             const __nv_bfloat16* __restrict__ Bh, const __nv_bfloat16* __restrict__ Bl,
             const float* __restrict__ bias,
             int M, int N, int K, const int* __restrict__ nsel, int mode) {
    extern __shared__ __nv_bfloat16 sdyn[];
    int tid = threadIdx.x;
    int bm = blockIdx.y * 128;
    int bn = blockIdx.x * 128;

    if (mode != 0) {
        int p0 = bm & 511;
        if (p0 >= nsel[bm >> 9]) return;
    }

    int wid = tid >> 5, lane = tid & 31;
    int m0 = (wid & 3) * 32, n0 = (wid >> 2) * 64;
    unsigned sbase = (unsigned)__cvta_generic_to_shared(sdyn);

    const __nv_bfloat16* gp[4];
    gp[0] = Ah; gp[1] = Al; gp[2] = Bh; gp[3] = Bl;
    int rbase[4] = {bm, bm, bn, bn};
    int id0 = tid * 2, id1 = tid * 2 + 1;
    int row0 = id0 >> 2, seg0 = (id0 & 3) * 8;
    int row1 = id1 >> 2, seg1 = (id1 & 3) * 8;

    float acc[2][8][4];
    #pragma unroll
    for (int i = 0; i < 2; i++)
        #pragma unroll
        for (int j = 0; j < 8; j++)
            #pragma unroll
            for (int c = 0; c < 4; c++) acc[i][j][c] = 0.f;

    uint4 rg[4][2];
    #pragma unroll
    for (int p = 0; p < 4; p++) {
        rg[p][0] = *(const uint4*)(gp[p] + (size_t)(rbase[p] + row0) * K + seg0);
        rg[p][1] = *(const uint4*)(gp[p] + (size_t)(rbase[p] + row1) * K + seg1);
    }
    #pragma unroll
    for (int p = 0; p < 4; p++) {
        __nv_bfloat16* sp = sdyn + (size_t)p * (128 * SAS);
        *(uint4*)&sp[row0 * SAS + seg0] = rg[p][0];
        *(uint4*)&sp[row1 * SAS + seg1] = rg[p][1];
    }
    __syncthreads();

    int alr = lane & 15, alh = (lane >> 4) * 16;
    int bro = ((lane >> 4) & 1) * 8 + (lane & 7);
    int bko = ((lane >> 3) & 1) * 16;

    int nslab = K >> 5;
    for (int sl = 0; sl < nslab; sl++) {
        int buf = sl & 1;
        if (sl + 1 < nslab) {
            int k0 = (sl + 1) * 32;
            #pragma unroll
            for (int p = 0; p < 4; p++) {
                rg[p][0] = *(const uint4*)(gp[p] + (size_t)(rbase[p] + row0) * K + k0 + seg0);
                rg[p][1] = *(const uint4*)(gp[p] + (size_t)(rbase[p] + row1) * K + k0 + seg1);
            }
        }
        unsigned base = sbase + (unsigned)buf * (4 * OPSZ);
        #pragma unroll
        for (int kk = 0; kk < 32; kk += 16) {
            unsigned ah[2][4], al[2][4], bh[4][4], bl[4][4];
            #pragma unroll
            for (int i = 0; i < 2; i++) {
                unsigned ra = base + ((m0 + 16 * i + alr) * SAS + kk) * 2 + alh;
                ldm4(ah[i], ra);
                ldm4(al[i], ra + OPSZ);
            }
            #pragma unroll
            for (int g = 0; g < 4; g++) {
                unsigned rb = base + 2 * OPSZ + ((n0 + 16 * g + bro) * SAS + kk) * 2 + bko;
                ldm4(bh[g], rb);
                ldm4(bl[g], rb + OPSZ);
            }
            #pragma unroll
            for (int i = 0; i < 2; i++)
                #pragma unroll
                for (int g = 0; g < 4; g++)
                    #pragma unroll
                    for (int h = 0; h < 2; h++) {
                        int j = 2 * g + h;
                        mma16816(acc[i][j], ah[i], bh[g][2*h], bh[g][2*h + 1]);
                        mma16816(acc[i][j], ah[i], bl[g][2*h], bl[g][2*h + 1]);
                        mma16816(acc[i][j], al[i], bh[g][2*h], bh[g][2*h + 1]);
                    }
        }
        if (sl + 1 < nslab) {
            int nb = buf ^ 1;
            #pragma unroll
            for (int p = 0; p < 4; p++) {
                __nv_bfloat16* sp = sdyn + (size_t)(nb * 4 + p) * (128 * SAS);
                *(uint4*)&sp[row0 * SAS + seg0] = rg[p][0];
                *(uint4*)&sp[row1 * SAS + seg1] = rg[p][1];
            }
            __syncthreads();
        }
    }
    #pragma unroll
    for (int i = 0; i < 2; i++) {
        int rA = bm + m0 + 16 * i + (lane >> 2);
        #pragma unroll
        for (int j = 0; j < 8; j++) {
            int col = bn + n0 + 8 * j + 2 * (lane & 3);
            float b0v = 0.f, b1v = 0.f;
            if (bias) { b0v = bias[col]; b1v = bias[col + 1]; }
            *(float2*)(C + (size_t)rA * N + col) =
                make_float2(acc[i][j][0] + b0v, acc[i][j][1] + b1v);
            *(float2*)(C + (size_t)(rA + 8) * N + col) =
                make_float2(acc[i][j][2] + b0v, acc[i][j][3] + b1v);
        }
    }
}

// ---------------------------------------------------------------------------
// split-bf16 GEMM, 3-plane / 6-term (selector; error ~2^-23, near-fp32)
// ---------------------------------------------------------------------------
__global__ __launch_bounds__(256, 1)
void k_bgemm3(float* __restrict__ C,
              const __nv_bfloat16* __restrict__ A1, const __nv_bfloat16* __restrict__ A2,
              const __nv_bfloat16* __restrict__ A3,
              const __nv_bfloat16* __restrict__ B1, const __nv_bfloat16* __restrict__ B2,
              const __nv_bfloat16* __restrict__ B3,
              const float* __restrict__ bias, int M, int N, int K) {
    extern __shared__ __nv_bfloat16 sdyn[];
    int tid = threadIdx.x;
    int bm = blockIdx.y * 128;
    int bn = blockIdx.x * 128;
    int wid = tid >> 5, lane = tid & 31;
    int m0 = (wid & 3) * 32, n0 = (wid >> 2) * 64;
    unsigned sbase = (unsigned)__cvta_generic_to_shared(sdyn);

    const __nv_bfloat16* gp[6];
    gp[0] = A1; gp[1] = A2; gp[2] = A3; gp[3] = B1; gp[4] = B2; gp[5] = B3;
    int rbase[6] = {bm, bm, bm, bn, bn, bn};
    int id0 = tid * 2, id1 = tid * 2 + 1;
    int row0 = id0 >> 2, seg0 = (id0 & 3) * 8;
    int row1 = id1 >> 2, seg1 = (id1 & 3) * 8;

    float acc[2][8][4];
    #pragma unroll
    for (int i = 0; i < 2; i++)
        #pragma unroll
        for (int j = 0; j < 8; j++)
            #pragma unroll
            for (int c = 0; c < 4; c++) acc[i][j][c] = 0.f;

    uint4 rg[6][2];
    #pragma unroll
    for (int p = 0; p < 6; p++) {
        rg[p][0] = *(const uint4*)(gp[p] + (size_t)(rbase[p] + row0) * K + seg0);
        rg[p][1] = *(const uint4*)(gp[p] + (size_t)(rbase[p] + row1) * K + seg1);
    }
    #pragma unroll
    for (int p = 0; p < 6; p++) {
        __nv_bfloat16* sp = sdyn + (size_t)p * (128 * SAS);
        *(uint4*)&sp[row0 * SAS + seg0] = rg[p][0];
        *(uint4*)&sp[row1 * SAS + seg1] = rg[p][1];
    }
    __syncthreads();

    int alr = lane & 15, alh = (lane >> 4) * 16;
    int bro = ((lane >> 4) & 1) * 8 + (lane & 7);
    int bko = ((lane >> 3) & 1) * 16;

    int nslab = K >> 5;
    for (int sl = 0; sl < nslab; sl++) {
        int buf = sl & 1;
        if (sl + 1 < nslab) {
            int k0 = (sl + 1) * 32;
            #pragma unroll
            for (int p = 0; p < 6; p++) {
                rg[p][0] = *(const uint4*)(gp[p] + (size_t)(rbase[p] + row0) * K + k0 + seg0);
                rg[p][1] = *(const uint4*)(gp[p] + (size_t)(rbase[p] + row1) * K + k0 + seg1);
            }
        }
        unsigned base = sbase + (unsigned)buf * (6 * OPSZ);
        #pragma unroll
        for (int kk = 0; kk < 32; kk += 16) {
            unsigned a1[2][4], a2[2][4], a3[2][4];
            unsigned b1[4][4], b2[4][4], b3[4][4];
            #pragma unroll
            for (int i = 0; i < 2; i++) {
                unsigned ra = base + ((m0 + 16 * i + alr) * SAS + kk) * 2 + alh;
                ldm4(a1[i], ra);
                ldm4(a2[i], ra + OPSZ);
                ldm4(a3[i], ra + 2 * OPSZ);
            }
            #pragma unroll
            for (int g = 0; g < 4; g++) {
                unsigned rb = base + 3 * OPSZ + ((n0 + 16 * g + bro) * SAS + kk) * 2 + bko;
                ldm4(b1[g], rb);
                ldm4(b2[g], rb + OPSZ);
                ldm4(b3[g], rb + 2 * OPSZ);
            }
            #pragma unroll
            for (int i = 0; i < 2; i++)
                #pragma unroll
                for (int g = 0; g < 4; g++)
                    #pragma unroll
                    for (int h = 0; h < 2; h++) {
                        int j = 2 * g + h;
                        mma16816(acc[i][j], a1[i], b1[g][2*h], b1[g][2*h + 1]);
                        mma16816(acc[i][j], a1[i], b2[g][2*h], b2[g][2*h + 1]);
                        mma16816(acc[i][j], a2[i], b1[g][2*h], b1[g][2*h + 1]);
                        mma16816(acc[i][j], a1[i], b3[g][2*h], b3[g][2*h + 1]);
                        mma16816(acc[i][j], a2[i], b2[g][2*h], b2[g][2*h + 1]);
                        mma16816(acc[i][j], a3[i], b1[g][2*h], b1[g][2*h + 1]);
                    }
        }
        if (sl + 1 < nslab) {
            int nb = buf ^ 1;
            #pragma unroll
            for (int p = 0; p < 6; p++) {
                __nv_bfloat16* sp = sdyn + (size_t)(nb * 6 + p) * (128 * SAS);
                *(uint4*)&sp[row0 * SAS + seg0] = rg[p][0];
                *(uint4*)&sp[row1 * SAS + seg1] = rg[p][1];
            }
            __syncthreads();
        }
    }
    #pragma unroll
    for (int i = 0; i < 2; i++) {
        int rA = bm + m0 + 16 * i + (lane >> 2);
        #pragma unroll
        for (int j = 0; j < 8; j++) {
            int col = bn + n0 + 8 * j + 2 * (lane & 3);
            float b0v = 0.f, b1v = 0.f;
            if (bias) { b0v = bias[col]; b1v = bias[col + 1]; }
            *(float2*)(C + (size_t)rA * N + col) =
                make_float2(acc[i][j][0] + b0v, acc[i][j][1] + b1v);
            *(float2*)(C + (size_t)(rA + 8) * N + col) =
                make_float2(acc[i][j][2] + b0v, acc[i][j][3] + b1v);
        }
    }
}

// ---------------------------------------------------------------------------
// tensor-core GRU recurrence, 2-plane / 3-term (layers 0/1), 512 threads.
// Output bf16 planes; history stores moved AFTER the release (off the
// inter-CTA critical path).
// ---------------------------------------------------------------------------
__global__ __launch_bounds__(512, 1)
void k_recur_mma(const float* __restrict__ Gi,
                 __nv_bfloat16* __restrict__ outH, __nv_bfloat16* __restrict__ outL,
                 const __nv_bfloat16* __restrict__ Wh,
                 const __nv_bfloat16* __restrict__ Wl,
                 const float* __restrict__ bhh, const int* __restrict__ nsel) {
    extern __shared__ __nv_bfloat16 smb[];
    float* red = (float*)(smb + MSM_BF);
    int tid = threadIdx.x;
    int bt = blockIdx.x & 3, jt = blockIdx.x >> 2;
    int b0 = bt * 16, j0 = jt * 16;
    int wid = tid >> 5, lane = tid & 31;
    int jj = tid & 15, bb2 = tid >> 4;
    bool ph2 = tid < 256;
    int j2 = j0 + jj;
    int b2 = b0 + (bb2 & 15);

    for (int idx = tid; idx < 48 * 512; idx += 512) {
        int r = idx >> 9, k = idx & 511;
        int g = r >> 4, jl = r & 15;
        size_t grow = (size_t)(g * 512 + j0 + jl) * 512 + k;
        smb[MSM_W  + r * SWS + k] = Wh[grow];
        smb[MSM_WL + r * SWS + k] = Wl[grow];
    }
    float br = bhh[j2], bz = bhh[512 + j2], bn2 = bhh[1024 + j2];
    int lim = ph2 ? nsel[b2] : TT;
    int maxlim = 0;
    #pragma unroll
    for (int b = 0; b < 16; b++) {
        int v = nsel[b0 + b];
        maxlim = v > maxlim ? v : maxlim;
    }
    unsigned* barp = &g_bar4[bt * 32];
    unsigned sbase = (unsigned)__cvta_generic_to_shared(smb);

    int alr = lane & 15, alh = (lane >> 4) * 16;
    int bro = ((lane >> 4) & 1) * 8 + (lane & 7);
    int bko = ((lane >> 3) & 1) * 16;

    __syncthreads();

    for (int t = 0; t < maxlim; t++) {
        float gir = 0.f, giz = 0.f, gin = 0.f;
        if (ph2) {
            const float* gp = Gi + ((size_t)b2 * TT + t) * G3;
            gir = __ldcg(gp + j2);
            giz = __ldcg(gp + 512 + j2);
            gin = __ldcg(gp + 1024 + j2);
        }

        if (t > 0) {
            if (tid == 0) {
                unsigned tgt = 32u * (unsigned)t;
                while (ld_acq(barp) < tgt) { }
            }
            __syncthreads();
        }

        const float* hsrc = g_h[t & 1];
        float hold = 0.f;
        if (ph2) hold = __ldcg(hsrc + (size_t)b2 * HH + j2);
        #pragma unroll
        for (int i = 0; i < 4; i++) {
            int id = tid + i * 512;
            int lb = id >> 7;
            int lk = (id & 127) * 4;
            float4 v = __ldcg((const float4*)(hsrc + (size_t)(b0 + lb) * HH + lk));
            __nv_bfloat162 h01 = __floats2bfloat162_rn(v.x, v.y);
            __nv_bfloat162 h23 = __floats2bfloat162_rn(v.z, v.w);
            __nv_bfloat162 l01 = __floats2bfloat162_rn(v.x - __low2float(h01),
                                                       v.y - __high2float(h01));
            __nv_bfloat162 l23 = __floats2bfloat162_rn(v.z - __low2float(h23),
                                                       v.w - __high2float(h23));
            int off = lb * SWS + lk;
            *(__nv_bfloat162*)&smb[MSM_HH + off]     = h01;
            *(__nv_bfloat162*)&smb[MSM_HH + off + 2] = h23;
            *(__nv_bfloat162*)&smb[MSM_HL + off]     = l01;
            *(__nv_bfloat162*)&smb[MSM_HL + off + 2] = l23;
        }
        __syncthreads();

        if (wid < 12) {
            int gt = wid % 3, kq = wid / 3;
            float acc0[4] = {0.f, 0.f, 0.f, 0.f};
            float acc1[4] = {0.f, 0.f, 0.f, 0.f};
            #pragma unroll
            for (int ks = 0; ks < 8; ks++) {
                int kk = kq * 128 + ks * 16;
                unsigned ah[4], al[4], bh[4], bl[4];
                unsigned ra = sbase + (unsigned)(MSM_HH + alr * SWS + kk) * 2 + alh;
                ldm4(ah, ra);
                ldm4(al, ra + (MSM_HL - MSM_HH) * 2);
                unsigned rb = sbase + (unsigned)((gt * 16 + bro) * SWS + kk) * 2 + bko;
                ldm4(bh, rb);
                ldm4(bl, rb + MSM_WL * 2);
                mma16816(acc0, ah, bh[0], bh[1]);
                mma16816(acc0, ah, bl[0], bl[1]);
                mma16816(acc0, al, bh[0], bh[1]);
                mma16816(acc1, ah, bh[2], bh[3]);
                mma16816(acc1, ah, bl[2], bl[3]);
                mma16816(acc1, al, bh[2], bh[3]);
            }
            int r = lane >> 2, c2 = 2 * (lane & 3);
            float* rp = red + (kq * 16 + r) * MRED_STR + gt * 16;
            *(float2*)(rp + c2)                    = make_float2(acc0[0], acc0[1]);
            *(float2*)(rp + 8 * MRED_STR + c2)     = make_float2(acc0[2], acc0[3]);
            *(float2*)(rp + 8 + c2)                = make_float2(acc1[0], acc1[1]);
            *(float2*)(rp + 8 * MRED_STR + 8 + c2) = make_float2(acc1[2], acc1[3]);
        }
        __syncthreads();

        float y = 0.f;
        bool valid = false;
        if (ph2) {
            float sr = br, sz = bz, sn = bn2;
            #pragma unroll
            for (int kq = 0; kq < 4; kq++) {
                const float* rp = red + (kq * 16 + (bb2 & 15)) * MRED_STR;
                sr += rp[jj];
                sz += rp[16 + jj];
                sn += rp[32 + jj];
            }
            float r_ = 1.f / (1.f + expf(-(gir + sr)));
            float z  = 1.f / (1.f + expf(-(giz + sz)));
            float n  = tanhf(gin + r_ * sn);
            float hn = (1.f - z) * n + z * hold;
            valid = t < lim;
            g_h[(t + 1) & 1][b2 * HH + j2] = valid ? hn : hold;
            y = valid ? hn : 0.f;
        }

        __syncthreads();
        if (tid == 0) red_rel(barp);

        // history stores AFTER release: off the inter-CTA critical path
        if (ph2) {
            __nv_bfloat16 yh = __float2bfloat16(y);
            size_t oidx = ((size_t)b2 * TT + t) * HH + j2;
            outH[oidx] = yh;
            outL[oidx] = __float2bfloat16(y - __bfloat162float(yh));
        }
    }

    if (ph2) {
        __nv_bfloat16 zb = __float2bfloat16(0.f);
        for (int t = maxlim; t < TT; t++) {
            size_t oidx = ((size_t)b2 * TT + t) * HH + j2;
            outH[oidx] = zb;
            outL[oidx] = zb;
        }
    }
}

// ---------------------------------------------------------------------------
// tensor-core GRU recurrence, 3-plane / 6-term (selector), 512 threads.
// ---------------------------------------------------------------------------
__global__ __launch_bounds__(512, 1)
void k_recur_mma3(const float* __restrict__ Gi, float* __restrict__ hist,
                  const __nv_bfloat16* __restrict__ W1,
                  const __nv_bfloat16* __restrict__ W2,
                  const __nv_bfloat16* __restrict__ W3,
                  const float* __restrict__ bhh) {
    extern __shared__ __nv_bfloat16 smb[];
    float* red = (float*)(smb + M3_BF);
    int tid = threadIdx.x;
    int bt = blockIdx.x & 3, jt = blockIdx.x >> 2;
    int b0 = bt * 16, j0 = jt * 16;
    int wid = tid >> 5, lane = tid & 31;
    int jj = tid & 15, bb2 = tid >> 4;
    bool ph2 = tid < 256;
    int j2 = j0 + jj;
    int b2 = b0 + (bb2 & 15);

    for (int idx = tid; idx < 48 * 512; idx += 512) {
        int r = idx >> 9, k = idx & 511;
        int g = r >> 4, jl = r & 15;
        size_t grow = (size_t)(g * 512 + j0 + jl) * 512 + k;
        smb[M3_W1 + r * SWS + k] = W1[grow];
        smb[M3_W2 + r * SWS + k] = W2[grow];
        smb[M3_W3 + r * SWS + k] = W3[grow];
    }
    float br = bhh[j2], bz = bhh[512 + j2], bn2 = bhh[1024 + j2];
    unsigned* barp = &g_bar4[bt * 32];
    unsigned sbase = (unsigned)__cvta_generic_to_shared(smb);

    int alr = lane & 15, alh = (lane >> 4) * 16;
    int bro = ((lane >> 4) & 1) * 8 + (lane & 7);
    int bko = ((lane >> 3) & 1) * 16;

    __syncthreads();

    for (int t = 0; t < TT; t++) {
        float gir = 0.f, giz = 0.f, gin = 0.f;
        if (ph2) {
            const float* gp = Gi + ((size_t)b2 * TT + t) * G3;
            gir = __ldcg(gp + j2);
            giz = __ldcg(gp + 512 + j2);
            gin = __ldcg(gp + 1024 + j2);
        }

        if (t > 0) {
            if (tid == 0) {
                unsigned tgt = 32u * (unsigned)t;
                while (ld_acq(barp) < tgt) { }
            }
            __syncthreads();
        }

        const float* hsrc = g_h[t & 1];
        float hold = 0.f;
        if (ph2) hold = __ldcg(hsrc + (size_t)b2 * HH + j2);
        #pragma unroll
        for (int i = 0; i < 4; i++) {
            int id = tid + i * 512;
            int lb = id >> 7;
            int lk = (id & 127) * 4;
            float4 v = __ldcg((const float4*)(hsrc + (size_t)(b0 + lb) * HH + lk));
            float xs[4] = {v.x, v.y, v.z, v.w};
            __nv_bfloat16 h1[4], h2[4], h3[4];
            #pragma unroll
            for (int c = 0; c < 4; c++) {
                h1[c] = __float2bfloat16(xs[c]);
                float r = xs[c] - __bfloat162float(h1[c]);
                h2[c] = __float2bfloat16(r);
                float r2 = r - __bfloat162float(h2[c]);
                h3[c] = __float2bfloat16(r2);
            }
            int off = lb * SWS + lk;
            *(__nv_bfloat162*)&smb[M3_H1 + off]     = *(__nv_bfloat162*)&h1[0];
            *(__nv_bfloat162*)&smb[M3_H1 + off + 2] = *(__nv_bfloat162*)&h1[2];
            *(__nv_bfloat162*)&smb[M3_H2 + off]     = *(__nv_bfloat162*)&h2[0];
            *(__nv_bfloat162*)&smb[M3_H2 + off + 2] = *(__nv_bfloat162*)&h2[2];
            *(__nv_bfloat162*)&smb[M3_H3 + off]     = *(__nv_bfloat162*)&h3[0];
            *(__nv_bfloat162*)&smb[M3_H3 + off + 2] = *(__nv_bfloat162*)&h3[2];
        }
        __syncthreads();

        if (wid < 12) {
            int gt = wid % 3, kq = wid / 3;
            float acc0[4] = {0.f, 0.f, 0.f, 0.f};
            float acc1[4] = {0.f, 0.f, 0.f, 0.f};
            #pragma unroll
            for (int ks = 0; ks < 8; ks++) {
                int kk = kq * 128 + ks * 16;
                unsigned a1[4], a2[4], a3[4], b1[4], b2[4], b3[4];
                unsigned ra = sbase + (unsigned)(M3_H1 + alr * SWS + kk) * 2 + alh;
                ldm4(a1, ra);
                ldm4(a2, ra + (M3_H2 - M3_H1) * 2);
                ldm4(a3, ra + (M3_H3 - M3_H1) * 2);
                unsigned rb = sbase + (unsigned)((gt * 16 + bro) * SWS + kk) * 2 + bko;
                ldm4(b1, rb);
                ldm4(b2, rb + M3_W2 * 2);
                ldm4(b3, rb + M3_W3 * 2);
                mma16816(acc0, a1, b1[0], b1[1]);
                mma16816(acc0, a1, b2[0], b2[1]);
                mma16816(acc0, a2, b1[0], b1[1]);
                mma16816(acc0, a1, b3[0], b3[1]);
                mma16816(acc0, a2, b2[0], b2[1]);
                mma16816(acc0, a3, b1[0], b1[1]);
                mma16816(acc1, a1, b1[2], b1[3]);
                mma16816(acc1, a1, b2[2], b2[3]);
                mma16816(acc1, a2, b1[2], b1[3]);
                mma16816(acc1, a1, b3[2], b3[3]);
                mma16816(acc1, a2, b2[2], b2[3]);
                mma16816(acc1, a3, b1[2], b1[3]);
            }
            int r = lane >> 2, c2 = 2 * (lane & 3);
            float* rp = red + (kq * 16 + r) * MRED_STR + gt * 16;
            *(float2*)(rp + c2)                    = make_float2(acc0[0], acc0[1]);
            *(float2*)(rp + 8 * MRED_STR + c2)     = make_float2(acc0[2], acc0[3]);
            *(float2*)(rp + 8 + c2)                = make_float2(acc1[0], acc1[1]);
            *(float2*)(rp + 8 * MRED_STR + 8 + c2) = make_float2(acc1[2], acc1[3]);
        }
        __syncthreads();

        float hn = 0.f;
        if (ph2) {
            float sr = br, sz = bz, sn = bn2;
            #pragma unroll
            for (int kq = 0; kq < 4; kq++) {
                const float* rp = red + (kq * 16 + (bb2 & 15)) * MRED_STR;
                sr += rp[jj];
                sz += rp[16 + jj];
                sn += rp[32 + jj];
            }
            float r_ = 1.f / (1.f + expf(-(gir + sr)));
            float z  = 1.f / (1.f + expf(-(giz + sz)));
            float n  = tanhf(gin + r_ * sn);
            hn = (1.f - z) * n + z * hold;
            g_h[(t + 1) & 1][b2 * HH + j2] = hn;
        }

        __syncthreads();
        if (tid == 0) red_rel(barp);

        // hist store AFTER release (off the inter-CTA critical path)
        if (ph2)
            hist[((size_t)b2 * TT + t) * HH + j2] = hn;
    }
}

// ---------------------------------------------------------------------------
__global__ void k_selargmax(const float* __restrict__ hist,
                            const float* __restrict__ Ws,
                            const float* __restrict__ bs) {
    int gw = (blockIdx.x * blockDim.x + threadIdx.x) >> 5;
    int lane = threadIdx.x & 31;
    if (gw >= BB * TT) return;
    const float* h = hist + (size_t)gw * HH;
    float l0 = 0.f, l1 = 0.f;
    #pragma unroll 4
    for (int jv = lane; jv < HH; jv += 32) {
        float hv = h[jv];
        l0 += hv * Ws[jv];
        l1 += hv * Ws[HH + jv];
    }
    #pragma unroll
    for (int o = 16; o; o >>= 1) {
        l0 += __shfl_down_sync(0xffffffffu, l0, o);
        l1 += __shfl_down_sync(0xffffffffu, l1, o);
    }
    if (lane == 0)
        g_sel[gw] = ((l1 + bs[1]) > (l0 + bs[0])) ? 1 : 0;
}

// ---------------------------------------------------------------------------
__global__ void k_fix(const int* __restrict__ mask) {
    int b = blockIdx.x;
    int lane = threadIdx.x;
    int len = 0;
    for (int t = lane; t < TT; t += 32) len += mask[b * TT + t];
    #pragma unroll
    for (int o = 16; o; o >>= 1) len += __shfl_down_sync(0xffffffffu, len, o);
    len = __shfl_sync(0xffffffffu, len, 0);
    int cnt = 0;
    for (int c = 0; c < TT; c += 32) {
        int t = c + lane;
        int s = g_sel[b * TT + t];
        if (t == 0) s = 1;
        if (t == len - 1) s = 1;
        if (t >= len) s = 0;
        unsigned bal = __ballot_sync(0xffffffffu, s);
        int pre = __popc(bal & ((1u << lane) - 1u));
        if (s) g_order[b * TT + cnt + pre] = t;
        cnt += __popc(bal);
    }
    if (lane == 0) g_nsel[b] = cnt;
}

// ---------------------------------------------------------------------------
// gather fused with 2-plane split: planes[b][p][:] = split(emb[b][order[p]][:])
// ---------------------------------------------------------------------------
__global__ void k_gather(const float* __restrict__ emb,
                         __nv_bfloat16* __restrict__ dH,
                         __nv_bfloat16* __restrict__ dL) {
    int row = blockIdx.x;               // b*T + p
    int b = row >> 9, p = row & 511;
    float4 v = make_float4(0.f, 0.f, 0.f, 0.f);
    if (p < g_nsel[b]) {
        int t = g_order[row];
        v = ((const float4*)(emb + ((size_t)b * TT + t) * EE))[threadIdx.x];
    }
    __nv_bfloat162 h01 = __floats2bfloat162_rn(v.x, v.y);
    __nv_bfloat162 h23 = __floats2bfloat162_rn(v.z, v.w);
    __nv_bfloat162 l01 = __floats2bfloat162_rn(v.x - __low2float(h01),
                                               v.y - __high2float(h01));
    __nv_bfloat162 l23 = __floats2bfloat162_rn(v.z - __low2float(h23),
                                               v.w - __high2float(h23));
    size_t off = (size_t)row * EE + threadIdx.x * 4;
    *(__nv_bfloat162*)(dH + off)     = h01;
    *(__nv_bfloat162*)(dH + off + 2) = h23;
    *(__nv_bfloat162*)(dL + off)     = l01;
    *(__nv_bfloat162*)(dL + off + 2) = l23;
}

// ---------------------------------------------------------------------------
// pool with exact nsel row-guard (U rows >= nsel are exact zeros; skipped
// tiles of U are never read).
// ---------------------------------------------------------------------------
__global__ void k_pool(const float* __restrict__ U, const float* __restrict__ bc,
                       int kw, int Nn, int seg) {
    int b = blockIdx.x;
    int f = threadIdx.x;
    int tlim = TT - kw + 1;
    int ns = g_nsel[b];
    int tcap = ns < tlim ? ns : tlim;
    int t0 = blockIdx.y * 64;
    int t1 = t0 + 64 < tlim ? t0 + 64 : tlim;
    float bcv = bc[f];
    float m = 0.f;
    if (t1 > tcap) m = fmaxf(bcv, 0.f);       // all-zero windows contribute relu(bc)
    int t1c = t1 < tcap ? t1 : tcap;
    const float* Ub = U + (size_t)b * TT * Nn + (size_t)f * kw;
    for (int t = t0; t < t1c; t++) {
        float s = bcv;
        int dtmax = ns - t; if (dtmax > kw) dtmax = kw;
        for (int dt = 0; dt < dtmax; dt++)
            s += Ub[(size_t)(t + dt) * Nn + dt];
        m = fmaxf(m, fmaxf(s, 0.f));
    }
    atomicMax((int*)&g_pooled[b * (3 * NF) + seg + f], __float_as_int(m));
}

// ---------------------------------------------------------------------------
__global__ void k_final(const float* __restrict__ Wo, const float* __restrict__ bo,
                        float* __restrict__ out) {
    __shared__ float redf[256];
    int b = blockIdx.x, tid = threadIdx.x;
    float s = 0.f;
    for (int f = tid; f < 3 * NF; f += 256)
        s += g_pooled[b * (3 * NF) + f] * Wo[f];
    redf[tid] = s;
    __syncthreads();
    for (int o = 128; o; o >>= 1) {
        if (tid < o) redf[tid] += redf[tid + o];
        __syncthreads();
    }
    if (tid == 0) out[b] = redf[0] + bo[0];
}

// ---------------------------------------------------------------------------
extern "C" void kernel_launch(void* const* d_in, const int* in_sizes, int n_in,
                              void* d_out, int out_size) {
    const float* emb   = (const float*)d_in[0];
    const int*   mask  = (const int*)  d_in[1];
    const float* Wih_c = (const float*)d_in[2];
    const float* Whh_c = (const float*)d_in[3];
    const float* bih_c = (const float*)d_in[4];
    const float* bhh_c = (const float*)d_in[5];
    const float* Ws    = (const float*)d_in[6];
    const float* bs    = (const float*)d_in[7];
    const float* Wih0  = (const float*)d_in[8];
    const float* Whh0  = (const float*)d_in[9];
    const float* bih0  = (const float*)d_in[10];
    const float* bhh0  = (const float*)d_in[11];
    const float* Wih1  = (const float*)d_in[12];
    const float* Whh1  = (const float*)d_in[13];
    const float* bih1  = (const float*)d_in[14];
    const float* bhh1  = (const float*)d_in[15];
    const float* Wc3   = (const float*)d_in[16];
    const float* bc3   = (const float*)d_in[17];
    const float* Wc4   = (const float*)d_in[18];
    const float* bc4   = (const float*)d_in[19];
    const float* Wc5   = (const float*)d_in[20];
    const float* bc5   = (const float*)d_in[21];
    const float* Wo    = (const float*)d_in[22];
    const float* bo    = (const float*)d_in[23];
    float* out = (float*)d_out;

    cudaFuncSetAttribute(k_recur_mma, cudaFuncAttributeMaxDynamicSharedMemorySize,
                         MSM_BYTES);
    cudaFuncSetAttribute(k_recur_mma3, cudaFuncAttributeMaxDynamicSharedMemorySize,
                         M3_BYTES);
    cudaFuncSetAttribute(k_bgemm, cudaFuncAttributeMaxDynamicSharedMemorySize,
                         BSM_BYTES);
    cudaFuncSetAttribute(k_bgemm3, cudaFuncAttributeMaxDynamicSharedMemorySize,
                         BSM3_BYTES);

    float *pGi, *pS0, *pU;
    int* pNsel;
    __nv_bfloat16 *pAh, *pAl, *pA3, *pWh, *pWl, *pW3;
    cudaGetSymbolAddress((void**)&pGi,   g_Gi);
    cudaGetSymbolAddress((void**)&pS0,   g_seq0);
    cudaGetSymbolAddress((void**)&pU,    g_U);
    cudaGetSymbolAddress((void**)&pNsel, g_nsel);
    cudaGetSymbolAddress((void**)&pAh,   g_Ah);
    cudaGetSymbolAddress((void**)&pAl,   g_Al);
    cudaGetSymbolAddress((void**)&pA3,   g_A3);
    cudaGetSymbolAddress((void**)&pWh,   g_Wh);
    cudaGetSymbolAddress((void**)&pWl,   g_Wl);
    cudaGetSymbolAddress((void**)&pW3,   g_W3);

    const size_t nAE = (size_t)MALL * EE;

    // ---- selector GRU: 3-plane/6-term bf16 tensor path (near-fp32 exact) ----
    k_split3<<<(int)((nAE + 255)/256), 256>>>(emb, pAh, pAl, pA3, nAE);
    k_split3<<<(G3*EE + 255)/256, 256>>>(Wih_c, pWh, pWl, pW3, (size_t)G3*EE);
    k_bgemm3<<<dim3(G3/128, MALL/128), 256, BSM3_BYTES>>>(
        pGi, pAh, pAl, pA3, pWh, pWl, pW3, bih_c, MALL, G3, EE);
    k_split3<<<(G3*HH + 255)/256, 256>>>(Whh_c, pWh, pWl, pW3, (size_t)G3*HH);
    k_reset<<<256, 256>>>();
    k_recur_mma3<<<NBLK, 512, M3_BYTES>>>(pGi, pS0, pWh, pWl, pW3, bhh_c);
    k_selargmax<<<(BB*TT*32 + 255)/256, 256>>>(pS0, Ws, bs);
    k_fix<<<BB, 32>>>(mask);
    // gather fused with split -> planes (overwrites selector A planes, done)
    k_gather<<<MALL, EE/4>>>(emb, pAh, pAl);

    // ---- layer 0: bgemm on gathered planes, recurrence emits planes ----
    k_split<<<(G3*EE + 255)/256, 256>>>(Wih0, pWh, pWl, (size_t)G3*EE);
    k_bgemm<<<dim3(G3/128, MALL/128), 256, BSM_BYTES>>>(
        pGi, pAh, pAl, pWh, pWl, bih0, MALL, G3, EE, pNsel, 1);
    k_split<<<(G3*HH + 255)/256, 256>>>(Whh0, pWh, pWl, (size_t)G3*HH);
    k_reset<<<256, 256>>>();
    k_recur_mma<<<NBLK, 512, MSM_BYTES>>>(pGi, pAh, pAl, pWh, pWl, bhh0, pNsel);

    // ---- layer 1 ----
    k_split<<<(G3*HH + 255)/256, 256>>>(Wih1, pWh, pWl, (size_t)G3*HH);
    k_bgemm<<<dim3(G3/128, MALL/128), 256, BSM_BYTES>>>(
        pGi, pAh, pAl, pWh, pWl, bih1, MALL, G3, HH, pNsel, 1);
    k_split<<<(G3*HH + 255)/256, 256>>>(Whh1, pWh, pWl, (size_t)G3*HH);
    k_reset<<<256, 256>>>();
    k_recur_mma<<<NBLK, 512, MSM_BYTES>>>(pGi, pAh, pAl, pWh, pWl, bhh1, pNsel);

    // ---- convs (bgemm on out1 planes, skip tiles; pool guards rows) ----
    k_zero_pooled<<<(BB*3*NF + 255)/256, 256>>>();

    k_split<<<(NF*3*HH + 255)/256, 256>>>(Wc3, pWh, pWl, (size_t)NF*3*HH);
    k_bgemm<<<dim3((NF*3)/128, MALL/128), 256, BSM_BYTES>>>(
        pU, pAh, pAl, pWh, pWl, nullptr, MALL, NF*3, HH, pNsel, 1);
    k_pool<<<dim3(BB, 8), NF>>>(pU, bc3, 3, NF*3, 0);

    k_split<<<(NF*4*HH + 255)/256, 256>>>(Wc4, pWh, pWl, (size_t)NF*4*HH);
    k_bgemm<<<dim3((NF*4)/128, MALL/128), 256, BSM_BYTES>>>(
        pU, pAh, pAl, pWh, pWl, nullptr, MALL, NF*4, HH, pNsel, 1);
    k_pool<<<dim3(BB, 8), NF>>>(pU, bc4, 4, NF*4, NF);

    k_split<<<(NF*5*HH + 255)/256, 256>>>(Wc5, pWh, pWl, (size_t)NF*5*HH);
    k_bgemm<<<dim3((NF*5)/128, MALL/128), 256, BSM_BYTES>>>(
        pU, pAh, pAl, pWh, pWl, nullptr, MALL, NF*5, HH, pNsel, 1);
    k_pool<<<dim3(BB, 8), NF>>>(pU, bc5, 5, NF*5, 2*NF);

    // ---- final projection ----
    k_final<<<BB, 256>>>(Wo, bo, out);
}

// round 15
// speedup vs baseline: 1.0369x; 1.0369x over previous
#include <cuda_runtime.h>
#include <cuda_bf16.h>
#include <math.h>
#include <stdint.h>
#include <stddef.h>

typedef unsigned long long u64;

// Problem dims
#define BB    64
#define TT    512
#define EE    768
#define HH    512
#define G3    1536
#define NF    256
#define MALL  (BB*TT)          // 32768
#define NCV   (NF*12)          // 3072 combined conv output cols

#define NBLK      128

// -------- mma recurrence config (2-plane, layers) --------
#define SWS     520
#define MSM_W   0
#define MSM_WL  (48*SWS)
#define MSM_HH  (96*SWS)
#define MSM_HL  (112*SWS)
#define MSM_BF  (128*SWS)
#define MRED_STR 52
#define MSM_BYTES (MSM_BF*2 + 4*16*MRED_STR*4)   // 146432 B

// -------- mma recurrence config (3-plane, selector) --------
#define M3_W1  0
#define M3_W2  (48*SWS)
#define M3_W3  (96*SWS)
#define M3_H1  (144*SWS)
#define M3_H2  (160*SWS)
#define M3_H3  (176*SWS)
#define M3_BF  (192*SWS)
#define M3_BYTES (M3_BF*2 + 4*16*MRED_STR*4)     // 212992 B

// -------- bf16 tensor GEMM config --------
#define SAS   40
#define OPSZ  (128*SAS*2)
#define BSM_BYTES  (8*OPSZ)          // 2-plane: 2 bufs x 4 planes = 81920 B
#define BSM3_BYTES (12*OPSZ)         // 3-plane: 2 bufs x 6 planes = 122880 B

// ----------------- device scratch (statics; no cudaMalloc allowed) ----------
__device__ float g_Gi[(size_t)MALL * G3];
__device__ float g_seq0[(size_t)MALL * HH];    // selector hist (fp32, argmax)
__device__ float g_U[(size_t)MALL * NCV];
__device__ float g_h[2][BB * HH];
__device__ int   g_sel[BB * TT];
__device__ int   g_order[BB * TT];
__device__ int   g_nsel[BB];
__device__ float g_pooled[BB * 3 * NF];
__device__ unsigned g_bar4[4 * 32];
// bf16 split buffers (sized for max(G3*EE, NCV*HH))
__device__ __nv_bfloat16 g_Ah[(size_t)MALL * EE];
__device__ __nv_bfloat16 g_Al[(size_t)MALL * EE];
__device__ __nv_bfloat16 g_A3[(size_t)MALL * EE];
__device__ __nv_bfloat16 g_Wh[(size_t)NCV * HH];
__device__ __nv_bfloat16 g_Wl[(size_t)NCV * HH];
__device__ __nv_bfloat16 g_W3[G3 * EE];

// ----------------------------- sync helpers ---------------------------------
__device__ __forceinline__ unsigned ld_acq(const unsigned* p) {
    unsigned v;
    asm volatile("ld.acquire.gpu.global.u32 %0,[%1];" : "=r"(v) : "l"(p));
    return v;
}
__device__ __forceinline__ void red_rel(unsigned* p) {
    asm volatile("red.release.gpu.global.add.u32 [%0],1;" :: "l"(p));
}
// ----------------------------- mma helpers ----------------------------------
__device__ __forceinline__ void ldm4(unsigned* r, unsigned addr) {
    asm volatile("ldmatrix.sync.aligned.m8n8.x4.shared.b16 {%0,%1,%2,%3}, [%4];"
                 : "=r"(r[0]), "=r"(r[1]), "=r"(r[2]), "=r"(r[3]) : "r"(addr));
}
__device__ __forceinline__ void mma16816(float* c, const unsigned* a,
                                         unsigned b0, unsigned b1) {
    asm volatile("mma.sync.aligned.m16n8k16.row.col.f32.bf16.bf16.f32 "
                 "{%0,%1,%2,%3}, {%4,%5,%6,%7}, {%8,%9}, {%0,%1,%2,%3};"
                 : "+f"(c[0]), "+f"(c[1]), "+f"(c[2]), "+f"(c[3])
                 : "r"(a[0]), "r"(a[1]), "r"(a[2]), "r"(a[3]), "r"(b0), "r"(b1));
}

// ---------------------------------------------------------------------------
__global__ void k_reset() {
    int i = blockIdx.x * blockDim.x + threadIdx.x;
    if (i < 4 * 32) g_bar4[i] = 0u;
    if (i < 2 * BB * HH) ((float*)g_h)[i] = 0.f;
}
__global__ void k_zero_pooled() {
    int i = blockIdx.x * blockDim.x + threadIdx.x;
    if (i < BB * 3 * NF) g_pooled[i] = 0.f;
}
// split fp32 -> 2 bf16 planes
__global__ void k_split(const float* __restrict__ src,
                        __nv_bfloat16* __restrict__ p1,
                        __nv_bfloat16* __restrict__ p2, size_t n) {
    size_t i = (size_t)blockIdx.x * blockDim.x + threadIdx.x;
    if (i >= n) return;
    float x = src[i];
    __nv_bfloat16 h = __float2bfloat16(x);
    p1[i] = h;
    p2[i] = __float2bfloat16(x - __bfloat162float(h));
}
// split fp32 -> 3 bf16 planes (residual chain; combined error ~2^-24)
__global__ void k_split3(const float* __restrict__ src,
                         __nv_bfloat16* __restrict__ p1,
                         __nv_bfloat16* __restrict__ p2,
                         __nv_bfloat16* __restrict__ p3, size_t n) {
    size_t i = (size_t)blockIdx.x * blockDim.x + threadIdx.x;
    if (i >= n) return;
    float x = src[i];
    __nv_bfloat16 h1 = __float2bfloat16(x);
    float r = x - __bfloat162float(h1);
    __nv_bfloat16 h2 = __float2bfloat16(r);
    float r2 = r - __bfloat162float(h2);
    p1[i] = h1;
    p2[i] = h2;
    p3[i] = __float2bfloat16(r2);
}

// ---------------------------------------------------------------------------
// split-bf16 tensor-core GEMM, 2-plane / 3-term (layers + convs)
// mode 0 compute; mode 1 skip all-invalid 128-row tiles (no write).
// ---------------------------------------------------------------------------
__global__ __launch_bounds__(256, 1)
void k_bgemm(float* __restrict__ C,
             const __nv_bfloat16* __restrict__ Ah, const __nv_bfloat16* __restrict__ Al,
             const __nv_bfloat16* __restrict__ Bh, const __nv_bfloat16* __restrict__ Bl,
             const float* __restrict__ bias,
             int M, int N, int K, const int* __restrict__ nsel, int mode) {
    extern __shared__ __nv_bfloat16 sdyn[];
    int tid = threadIdx.x;
    int bm = blockIdx.y * 128;
    int bn = blockIdx.x * 128;

    if (mode != 0) {
        int p0 = bm & 511;
        if (p0 >= nsel[bm >> 9]) return;
    }

    int wid = tid >> 5, lane = tid & 31;
    int m0 = (wid & 3) * 32, n0 = (wid >> 2) * 64;
    unsigned sbase = (unsigned)__cvta_generic_to_shared(sdyn);

    const __nv_bfloat16* gp[4];
    gp[0] = Ah; gp[1] = Al; gp[2] = Bh; gp[3] = Bl;
    int rbase[4] = {bm, bm, bn, bn};
    int id0 = tid * 2, id1 = tid * 2 + 1;
    int row0 = id0 >> 2, seg0 = (id0 & 3) * 8;
    int row1 = id1 >> 2, seg1 = (id1 & 3) * 8;

    float acc[2][8][4];
    #pragma unroll
    for (int i = 0; i < 2; i++)
        #pragma unroll
        for (int j = 0; j < 8; j++)
            #pragma unroll
            for (int c = 0; c < 4; c++) acc[i][j][c] = 0.f;

    uint4 rg[4][2];
    #pragma unroll
    for (int p = 0; p < 4; p++) {
        rg[p][0] = *(const uint4*)(gp[p] + (size_t)(rbase[p] + row0) * K + seg0);
        rg[p][1] = *(const uint4*)(gp[p] + (size_t)(rbase[p] + row1) * K + seg1);
    }
    #pragma unroll
    for (int p = 0; p < 4; p++) {
        __nv_bfloat16* sp = sdyn + (size_t)p * (128 * SAS);
        *(uint4*)&sp[row0 * SAS + seg0] = rg[p][0];
        *(uint4*)&sp[row1 * SAS + seg1] = rg[p][1];
    }
    __syncthreads();

    int alr = lane & 15, alh = (lane >> 4) * 16;
    int bro = ((lane >> 4) & 1) * 8 + (lane & 7);
    int bko = ((lane >> 3) & 1) * 16;

    int nslab = K >> 5;
    for (int sl = 0; sl < nslab; sl++) {
        int buf = sl & 1;
        if (sl + 1 < nslab) {
            int k0 = (sl + 1) * 32;
            #pragma unroll
            for (int p = 0; p < 4; p++) {
                rg[p][0] = *(const uint4*)(gp[p] + (size_t)(rbase[p] + row0) * K + k0 + seg0);
                rg[p][1] = *(const uint4*)(gp[p] + (size_t)(rbase[p] + row1) * K + k0 + seg1);
            }
        }
        unsigned base = sbase + (unsigned)buf * (4 * OPSZ);
        #pragma unroll
        for (int kk = 0; kk < 32; kk += 16) {
            unsigned ah[2][4], al[2][4], bh[4][4], bl[4][4];
            #pragma unroll
            for (int i = 0; i < 2; i++) {
                unsigned ra = base + ((m0 + 16 * i + alr) * SAS + kk) * 2 + alh;
                ldm4(ah[i], ra);
                ldm4(al[i], ra + OPSZ);
            }
            #pragma unroll
            for (int g = 0; g < 4; g++) {
                unsigned rb = base + 2 * OPSZ + ((n0 + 16 * g + bro) * SAS + kk) * 2 + bko;
                ldm4(bh[g], rb);
                ldm4(bl[g], rb + OPSZ);
            }
            #pragma unroll
            for (int i = 0; i < 2; i++)
                #pragma unroll
                for (int g = 0; g < 4; g++)
                    #pragma unroll
                    for (int h = 0; h < 2; h++) {
                        int j = 2 * g + h;
                        mma16816(acc[i][j], ah[i], bh[g][2*h], bh[g][2*h + 1]);
                        mma16816(acc[i][j], ah[i], bl[g][2*h], bl[g][2*h + 1]);
                        mma16816(acc[i][j], al[i], bh[g][2*h], bh[g][2*h + 1]);
                    }
        }
        if (sl + 1 < nslab) {
            int nb = buf ^ 1;
            #pragma unroll
            for (int p = 0; p < 4; p++) {
                __nv_bfloat16* sp = sdyn + (size_t)(nb * 4 + p) * (128 * SAS);
                *(uint4*)&sp[row0 * SAS + seg0] = rg[p][0];
                *(uint4*)&sp[row1 * SAS + seg1] = rg[p][1];
            }
            __syncthreads();
        }
    }
    #pragma unroll
    for (int i = 0; i < 2; i++) {
        int rA = bm + m0 + 16 * i + (lane >> 2);
        #pragma unroll
        for (int j = 0; j < 8; j++) {
            int col = bn + n0 + 8 * j + 2 * (lane & 3);
            float b0v = 0.f, b1v = 0.f;
            if (bias) { b0v = bias[col]; b1v = bias[col + 1]; }
            *(float2*)(C + (size_t)rA * N + col) =
                make_float2(acc[i][j][0] + b0v, acc[i][j][1] + b1v);
            *(float2*)(C + (size_t)(rA + 8) * N + col) =
                make_float2(acc[i][j][2] + b0v, acc[i][j][3] + b1v);
        }
    }
}

// ---------------------------------------------------------------------------
// split-bf16 GEMM, 3-plane / 6-term (selector; error ~2^-23, near-fp32)
// ---------------------------------------------------------------------------
__global__ __launch_bounds__(256, 1)
void k_bgemm3(float* __restrict__ C,
              const __nv_bfloat16* __restrict__ A1, const __nv_bfloat16* __restrict__ A2,
              const __nv_bfloat16* __restrict__ A3,
              const __nv_bfloat16* __restrict__ B1, const __nv_bfloat16* __restrict__ B2,
              const __nv_bfloat16* __restrict__ B3,
              const float* __restrict__ bias, int M, int N, int K) {
    extern __shared__ __nv_bfloat16 sdyn[];
    int tid = threadIdx.x;
    int bm = blockIdx.y * 128;
    int bn = blockIdx.x * 128;
    int wid = tid >> 5, lane = tid & 31;
    int m0 = (wid & 3) * 32, n0 = (wid >> 2) * 64;
    unsigned sbase = (unsigned)__cvta_generic_to_shared(sdyn);

    const __nv_bfloat16* gp[6];
    gp[0] = A1; gp[1] = A2; gp[2] = A3; gp[3] = B1; gp[4] = B2; gp[5] = B3;
    int rbase[6] = {bm, bm, bm, bn, bn, bn};
    int id0 = tid * 2, id1 = tid * 2 + 1;
    int row0 = id0 >> 2, seg0 = (id0 & 3) * 8;
    int row1 = id1 >> 2, seg1 = (id1 & 3) * 8;

    float acc[2][8][4];
    #pragma unroll
    for (int i = 0; i < 2; i++)
        #pragma unroll
        for (int j = 0; j < 8; j++)
            #pragma unroll
            for (int c = 0; c < 4; c++) acc[i][j][c] = 0.f;

    uint4 rg[6][2];
    #pragma unroll
    for (int p = 0; p < 6; p++) {
        rg[p][0] = *(const uint4*)(gp[p] + (size_t)(rbase[p] + row0) * K + seg0);
        rg[p][1] = *(const uint4*)(gp[p] + (size_t)(rbase[p] + row1) * K + seg1);
    }
    #pragma unroll
    for (int p = 0; p < 6; p++) {
        __nv_bfloat16* sp = sdyn + (size_t)p * (128 * SAS);
        *(uint4*)&sp[row0 * SAS + seg0] = rg[p][0];
        *(uint4*)&sp[row1 * SAS + seg1] = rg[p][1];
    }
    __syncthreads();

    int alr = lane & 15, alh = (lane >> 4) * 16;
    int bro = ((lane >> 4) & 1) * 8 + (lane & 7);
    int bko = ((lane >> 3) & 1) * 16;

    int nslab = K >> 5;
    for (int sl = 0; sl < nslab; sl++) {
        int buf = sl & 1;
        if (sl + 1 < nslab) {
            int k0 = (sl + 1) * 32;
            #pragma unroll
            for (int p = 0; p < 6; p++) {
                rg[p][0] = *(const uint4*)(gp[p] + (size_t)(rbase[p] + row0) * K + k0 + seg0);
                rg[p][1] = *(const uint4*)(gp[p] + (size_t)(rbase[p] + row1) * K + k0 + seg1);
            }
        }
        unsigned base = sbase + (unsigned)buf * (6 * OPSZ);
        #pragma unroll
        for (int kk = 0; kk < 32; kk += 16) {
            unsigned a1[2][4], a2[2][4], a3[2][4];
            unsigned b1[4][4], b2[4][4], b3[4][4];
            #pragma unroll
            for (int i = 0; i < 2; i++) {
                unsigned ra = base + ((m0 + 16 * i + alr) * SAS + kk) * 2 + alh;
                ldm4(a1[i], ra);
                ldm4(a2[i], ra + OPSZ);
                ldm4(a3[i], ra + 2 * OPSZ);
            }
            #pragma unroll
            for (int g = 0; g < 4; g++) {
                unsigned rb = base + 3 * OPSZ + ((n0 + 16 * g + bro) * SAS + kk) * 2 + bko;
                ldm4(b1[g], rb);
                ldm4(b2[g], rb + OPSZ);
                ldm4(b3[g], rb + 2 * OPSZ);
            }
            #pragma unroll
            for (int i = 0; i < 2; i++)
                #pragma unroll
                for (int g = 0; g < 4; g++)
                    #pragma unroll
                    for (int h = 0; h < 2; h++) {
                        int j = 2 * g + h;
                        mma16816(acc[i][j], a1[i], b1[g][2*h], b1[g][2*h + 1]);
                        mma16816(acc[i][j], a1[i], b2[g][2*h], b2[g][2*h + 1]);
                        mma16816(acc[i][j], a2[i], b1[g][2*h], b1[g][2*h + 1]);
                        mma16816(acc[i][j], a1[i], b3[g][2*h], b3[g][2*h + 1]);
                        mma16816(acc[i][j], a2[i], b2[g][2*h], b2[g][2*h + 1]);
                        mma16816(acc[i][j], a3[i], b1[g][2*h], b1[g][2*h + 1]);
                    }
        }
        if (sl + 1 < nslab) {
            int nb = buf ^ 1;
            #pragma unroll
            for (int p = 0; p < 6; p++) {
                __nv_bfloat16* sp = sdyn + (size_t)(nb * 6 + p) * (128 * SAS);
                *(uint4*)&sp[row0 * SAS + seg0] = rg[p][0];
                *(uint4*)&sp[row1 * SAS + seg1] = rg[p][1];
            }
            __syncthreads();
        }
    }
    #pragma unroll
    for (int i = 0; i < 2; i++) {
        int rA = bm + m0 + 16 * i + (lane >> 2);
        #pragma unroll
        for (int j = 0; j < 8; j++) {
            int col = bn + n0 + 8 * j + 2 * (lane & 3);
            float b0v = 0.f, b1v = 0.f;
            if (bias) { b0v = bias[col]; b1v = bias[col + 1]; }
            *(float2*)(C + (size_t)rA * N + col) =
                make_float2(acc[i][j][0] + b0v, acc[i][j][1] + b1v);
            *(float2*)(C + (size_t)(rA + 8) * N + col) =
                make_float2(acc[i][j][2] + b0v, acc[i][j][3] + b1v);
        }
    }
}

// ---------------------------------------------------------------------------
// tensor-core GRU recurrence, 2-plane / 3-term (layers 0/1), 512 threads.
// Output bf16 planes; history stores after the release.
// ---------------------------------------------------------------------------
__global__ __launch_bounds__(512, 1)
void k_recur_mma(const float* __restrict__ Gi,
                 __nv_bfloat16* __restrict__ outH, __nv_bfloat16* __restrict__ outL,
                 const __nv_bfloat16* __restrict__ Wh,
                 const __nv_bfloat16* __restrict__ Wl,
                 const float* __restrict__ bhh, const int* __restrict__ nsel) {
    extern __shared__ __nv_bfloat16 smb[];
    float* red = (float*)(smb + MSM_BF);
    int tid = threadIdx.x;
    int bt = blockIdx.x & 3, jt = blockIdx.x >> 2;
    int b0 = bt * 16, j0 = jt * 16;
    int wid = tid >> 5, lane = tid & 31;
    int jj = tid & 15, bb2 = tid >> 4;
    bool ph2 = tid < 256;
    int j2 = j0 + jj;
    int b2 = b0 + (bb2 & 15);

    for (int idx = tid; idx < 48 * 512; idx += 512) {
        int r = idx >> 9, k = idx & 511;
        int g = r >> 4, jl = r & 15;
        size_t grow = (size_t)(g * 512 + j0 + jl) * 512 + k;
        smb[MSM_W  + r * SWS + k] = Wh[grow];
        smb[MSM_WL + r * SWS + k] = Wl[grow];
    }
    float br = bhh[j2], bz = bhh[512 + j2], bn2 = bhh[1024 + j2];
    int lim = ph2 ? nsel[b2] : TT;
    int maxlim = 0;
    #pragma unroll
    for (int b = 0; b < 16; b++) {
        int v = nsel[b0 + b];
        maxlim = v > maxlim ? v : maxlim;
    }
    unsigned* barp = &g_bar4[bt * 32];
    unsigned sbase = (unsigned)__cvta_generic_to_shared(smb);

    int alr = lane & 15, alh = (lane >> 4) * 16;
    int bro = ((lane >> 4) & 1) * 8 + (lane & 7);
    int bko = ((lane >> 3) & 1) * 16;

    __syncthreads();

    for (int t = 0; t < maxlim; t++) {
        float gir = 0.f, giz = 0.f, gin = 0.f;
        if (ph2) {
            const float* gp = Gi + ((size_t)b2 * TT + t) * G3;
            gir = __ldcg(gp + j2);
            giz = __ldcg(gp + 512 + j2);
            gin = __ldcg(gp + 1024 + j2);
        }

        if (t > 0) {
            if (tid == 0) {
                unsigned tgt = 32u * (unsigned)t;
                while (ld_acq(barp) < tgt) { }
            }
            __syncthreads();
        }

        const float* hsrc = g_h[t & 1];
        float hold = 0.f;
        if (ph2) hold = __ldcg(hsrc + (size_t)b2 * HH + j2);
        #pragma unroll
        for (int i = 0; i < 4; i++) {
            int id = tid + i * 512;
            int lb = id >> 7;
            int lk = (id & 127) * 4;
            float4 v = __ldcg((const float4*)(hsrc + (size_t)(b0 + lb) * HH + lk));
            __nv_bfloat162 h01 = __floats2bfloat162_rn(v.x, v.y);
            __nv_bfloat162 h23 = __floats2bfloat162_rn(v.z, v.w);
            __nv_bfloat162 l01 = __floats2bfloat162_rn(v.x - __low2float(h01),
                                                       v.y - __high2float(h01));
            __nv_bfloat162 l23 = __floats2bfloat162_rn(v.z - __low2float(h23),
                                                       v.w - __high2float(h23));
            int off = lb * SWS + lk;
            *(__nv_bfloat162*)&smb[MSM_HH + off]     = h01;
            *(__nv_bfloat162*)&smb[MSM_HH + off + 2] = h23;
            *(__nv_bfloat162*)&smb[MSM_HL + off]     = l01;
            *(__nv_bfloat162*)&smb[MSM_HL + off + 2] = l23;
        }
        __syncthreads();

        if (wid < 12) {
            int gt = wid % 3, kq = wid / 3;
            float acc0[4] = {0.f, 0.f, 0.f, 0.f};
            float acc1[4] = {0.f, 0.f, 0.f, 0.f};
            #pragma unroll
            for (int ks = 0; ks < 8; ks++) {
                int kk = kq * 128 + ks * 16;
                unsigned ah[4], al[4], bh[4], bl[4];
                unsigned ra = sbase + (unsigned)(MSM_HH + alr * SWS + kk) * 2 + alh;
                ldm4(ah, ra);
                ldm4(al, ra + (MSM_HL - MSM_HH) * 2);
                unsigned rb = sbase + (unsigned)((gt * 16 + bro) * SWS + kk) * 2 + bko;
                ldm4(bh, rb);
                ldm4(bl, rb + MSM_WL * 2);
                mma16816(acc0, ah, bh[0], bh[1]);
                mma16816(acc0, ah, bl[0], bl[1]);
                mma16816(acc0, al, bh[0], bh[1]);
                mma16816(acc1, ah, bh[2], bh[3]);
                mma16816(acc1, ah, bl[2], bl[3]);
                mma16816(acc1, al, bh[2], bh[3]);
            }
            int r = lane >> 2, c2 = 2 * (lane & 3);
            float* rp = red + (kq * 16 + r) * MRED_STR + gt * 16;
            *(float2*)(rp + c2)                    = make_float2(acc0[0], acc0[1]);
            *(float2*)(rp + 8 * MRED_STR + c2)     = make_float2(acc0[2], acc0[3]);
            *(float2*)(rp + 8 + c2)                = make_float2(acc1[0], acc1[1]);
            *(float2*)(rp + 8 * MRED_STR + 8 + c2) = make_float2(acc1[2], acc1[3]);
        }
        __syncthreads();

        float y = 0.f;
        if (ph2) {
            float sr = br, sz = bz, sn = bn2;
            #pragma unroll
            for (int kq = 0; kq < 4; kq++) {
                const float* rp = red + (kq * 16 + (bb2 & 15)) * MRED_STR;
                sr += rp[jj];
                sz += rp[16 + jj];
                sn += rp[32 + jj];
            }
            float r_ = 1.f / (1.f + expf(-(gir + sr)));
            float z  = 1.f / (1.f + expf(-(giz + sz)));
            float n  = tanhf(gin + r_ * sn);
            float hn = (1.f - z) * n + z * hold;
            bool valid = t < lim;
            g_h[(t + 1) & 1][b2 * HH + j2] = valid ? hn : hold;
            y = valid ? hn : 0.f;
        }

        __syncthreads();
        if (tid == 0) red_rel(barp);

        if (ph2) {
            __nv_bfloat16 yh = __float2bfloat16(y);
            size_t oidx = ((size_t)b2 * TT + t) * HH + j2;
            outH[oidx] = yh;
            outL[oidx] = __float2bfloat16(y - __bfloat162float(yh));
        }
    }

    if (ph2) {
        __nv_bfloat16 zb = __float2bfloat16(0.f);
        for (int t = maxlim; t < TT; t++) {
            size_t oidx = ((size_t)b2 * TT + t) * HH + j2;
            outH[oidx] = zb;
            outL[oidx] = zb;
        }
    }
}

// ---------------------------------------------------------------------------
// tensor-core GRU recurrence, 3-plane / 6-term (selector), 512 threads.
// ---------------------------------------------------------------------------
__global__ __launch_bounds__(512, 1)
void k_recur_mma3(const float* __restrict__ Gi, float* __restrict__ hist,
                  const __nv_bfloat16* __restrict__ W1,
                  const __nv_bfloat16* __restrict__ W2,
                  const __nv_bfloat16* __restrict__ W3,
                  const float* __restrict__ bhh) {
    extern __shared__ __nv_bfloat16 smb[];
    float* red = (float*)(smb + M3_BF);
    int tid = threadIdx.x;
    int bt = blockIdx.x & 3, jt = blockIdx.x >> 2;
    int b0 = bt * 16, j0 = jt * 16;
    int wid = tid >> 5, lane = tid & 31;
    int jj = tid & 15, bb2 = tid >> 4;
    bool ph2 = tid < 256;
    int j2 = j0 + jj;
    int b2 = b0 + (bb2 & 15);

    for (int idx = tid; idx < 48 * 512; idx += 512) {
        int r = idx >> 9, k = idx & 511;
        int g = r >> 4, jl = r & 15;
        size_t grow = (size_t)(g * 512 + j0 + jl) * 512 + k;
        smb[M3_W1 + r * SWS + k] = W1[grow];
        smb[M3_W2 + r * SWS + k] = W2[grow];
        smb[M3_W3 + r * SWS + k] = W3[grow];
    }
    float br = bhh[j2], bz = bhh[512 + j2], bn2 = bhh[1024 + j2];
    unsigned* barp = &g_bar4[bt * 32];
    unsigned sbase = (unsigned)__cvta_generic_to_shared(smb);

    int alr = lane & 15, alh = (lane >> 4) * 16;
    int bro = ((lane >> 4) & 1) * 8 + (lane & 7);
    int bko = ((lane >> 3) & 1) * 16;

    __syncthreads();

    for (int t = 0; t < TT; t++) {
        float gir = 0.f, giz = 0.f, gin = 0.f;
        if (ph2) {
            const float* gp = Gi + ((size_t)b2 * TT + t) * G3;
            gir = __ldcg(gp + j2);
            giz = __ldcg(gp + 512 + j2);
            gin = __ldcg(gp + 1024 + j2);
        }

        if (t > 0) {
            if (tid == 0) {
                unsigned tgt = 32u * (unsigned)t;
                while (ld_acq(barp) < tgt) { }
            }
            __syncthreads();
        }

        const float* hsrc = g_h[t & 1];
        float hold = 0.f;
        if (ph2) hold = __ldcg(hsrc + (size_t)b2 * HH + j2);
        #pragma unroll
        for (int i = 0; i < 4; i++) {
            int id = tid + i * 512;
            int lb = id >> 7;
            int lk = (id & 127) * 4;
            float4 v = __ldcg((const float4*)(hsrc + (size_t)(b0 + lb) * HH + lk));
            float xs[4] = {v.x, v.y, v.z, v.w};
            __nv_bfloat16 h1[4], h2[4], h3[4];
            #pragma unroll
            for (int c = 0; c < 4; c++) {
                h1[c] = __float2bfloat16(xs[c]);
                float r = xs[c] - __bfloat162float(h1[c]);
                h2[c] = __float2bfloat16(r);
                float r2 = r - __bfloat162float(h2[c]);
                h3[c] = __float2bfloat16(r2);
            }
            int off = lb * SWS + lk;
            *(__nv_bfloat162*)&smb[M3_H1 + off]     = *(__nv_bfloat162*)&h1[0];
            *(__nv_bfloat162*)&smb[M3_H1 + off + 2] = *(__nv_bfloat162*)&h1[2];
            *(__nv_bfloat162*)&smb[M3_H2 + off]     = *(__nv_bfloat162*)&h2[0];
            *(__nv_bfloat162*)&smb[M3_H2 + off + 2] = *(__nv_bfloat162*)&h2[2];
            *(__nv_bfloat162*)&smb[M3_H3 + off]     = *(__nv_bfloat162*)&h3[0];
            *(__nv_bfloat162*)&smb[M3_H3 + off + 2] = *(__nv_bfloat162*)&h3[2];
        }
        __syncthreads();

        if (wid < 12) {
            int gt = wid % 3, kq = wid / 3;
            float acc0[4] = {0.f, 0.f, 0.f, 0.f};
            float acc1[4] = {0.f, 0.f, 0.f, 0.f};
            #pragma unroll
            for (int ks = 0; ks < 8; ks++) {
                int kk = kq * 128 + ks * 16;
                unsigned a1[4], a2[4], a3[4], b1[4], b2[4], b3[4];
                unsigned ra = sbase + (unsigned)(M3_H1 + alr * SWS + kk) * 2 + alh;
                ldm4(a1, ra);
                ldm4(a2, ra + (M3_H2 - M3_H1) * 2);
                ldm4(a3, ra + (M3_H3 - M3_H1) * 2);
                unsigned rb = sbase + (unsigned)((gt * 16 + bro) * SWS + kk) * 2 + bko;
                ldm4(b1, rb);
                ldm4(b2, rb + M3_W2 * 2);
                ldm4(b3, rb + M3_W3 * 2);
                mma16816(acc0, a1, b1[0], b1[1]);
                mma16816(acc0, a1, b2[0], b2[1]);
                mma16816(acc0, a2, b1[0], b1[1]);
                mma16816(acc0, a1, b3[0], b3[1]);
                mma16816(acc0, a2, b2[0], b2[1]);
                mma16816(acc0, a3, b1[0], b1[1]);
                mma16816(acc1, a1, b1[2], b1[3]);
                mma16816(acc1, a1, b2[2], b2[3]);
                mma16816(acc1, a2, b1[2], b1[3]);
                mma16816(acc1, a1, b3[2], b3[3]);
                mma16816(acc1, a2, b2[2], b2[3]);
                mma16816(acc1, a3, b1[2], b1[3]);
            }
            int r = lane >> 2, c2 = 2 * (lane & 3);
            float* rp = red + (kq * 16 + r) * MRED_STR + gt * 16;
            *(float2*)(rp + c2)                    = make_float2(acc0[0], acc0[1]);
            *(float2*)(rp + 8 * MRED_STR + c2)     = make_float2(acc0[2], acc0[3]);
            *(float2*)(rp + 8 + c2)                = make_float2(acc1[0], acc1[1]);
            *(float2*)(rp + 8 * MRED_STR + 8 + c2) = make_float2(acc1[2], acc1[3]);
        }
        __syncthreads();

        float hn = 0.f;
        if (ph2) {
            float sr = br, sz = bz, sn = bn2;
            #pragma unroll
            for (int kq = 0; kq < 4; kq++) {
                const float* rp = red + (kq * 16 + (bb2 & 15)) * MRED_STR;
                sr += rp[jj];
                sz += rp[16 + jj];
                sn += rp[32 + jj];
            }
            float r_ = 1.f / (1.f + expf(-(gir + sr)));
            float z  = 1.f / (1.f + expf(-(giz + sz)));
            float n  = tanhf(gin + r_ * sn);
            hn = (1.f - z) * n + z * hold;
            g_h[(t + 1) & 1][b2 * HH + j2] = hn;
        }

        __syncthreads();
        if (tid == 0) red_rel(barp);

        if (ph2)
            hist[((size_t)b2 * TT + t) * HH + j2] = hn;
    }
}

// ---------------------------------------------------------------------------
__global__ void k_selargmax(const float* __restrict__ hist,
                            const float* __restrict__ Ws,
                            const float* __restrict__ bs) {
    int gw = (blockIdx.x * blockDim.x + threadIdx.x) >> 5;
    int lane = threadIdx.x & 31;
    if (gw >= BB * TT) return;
    const float* h = hist + (size_t)gw * HH;
    float l0 = 0.f, l1 = 0.f;
    #pragma unroll 4
    for (int jv = lane; jv < HH; jv += 32) {
        float hv = h[jv];
        l0 += hv * Ws[jv];
        l1 += hv * Ws[HH + jv];
    }
    #pragma unroll
    for (int o = 16; o; o >>= 1) {
        l0 += __shfl_down_sync(0xffffffffu, l0, o);
        l1 += __shfl_down_sync(0xffffffffu, l1, o);
    }
    if (lane == 0)
        g_sel[gw] = ((l1 + bs[1]) > (l0 + bs[0])) ? 1 : 0;
}

// ---------------------------------------------------------------------------
__global__ void k_fix(const int* __restrict__ mask) {
    int b = blockIdx.x;
    int lane = threadIdx.x;
    int len = 0;
    for (int t = lane; t < TT; t += 32) len += mask[b * TT + t];
    #pragma unroll
    for (int o = 16; o; o >>= 1) len += __shfl_down_sync(0xffffffffu, len, o);
    len = __shfl_sync(0xffffffffu, len, 0);
    int cnt = 0;
    for (int c = 0; c < TT; c += 32) {
        int t = c + lane;
        int s = g_sel[b * TT + t];
        if (t == 0) s = 1;
        if (t == len - 1) s = 1;
        if (t >= len) s = 0;
        unsigned bal = __ballot_sync(0xffffffffu, s);
        int pre = __popc(bal & ((1u << lane) - 1u));
        if (s) g_order[b * TT + cnt + pre] = t;
        cnt += __popc(bal);
    }
    if (lane == 0) g_nsel[b] = cnt;
}

// ---------------------------------------------------------------------------
// gather fused with 2-plane split
// ---------------------------------------------------------------------------
__global__ void k_gather(const float* __restrict__ emb,
                         __nv_bfloat16* __restrict__ dH,
                         __nv_bfloat16* __restrict__ dL) {
    int row = blockIdx.x;               // b*T + p
    int b = row >> 9, p = row & 511;
    float4 v = make_float4(0.f, 0.f, 0.f, 0.f);
    if (p < g_nsel[b]) {
        int t = g_order[row];
        v = ((const float4*)(emb + ((size_t)b * TT + t) * EE))[threadIdx.x];
    }
    __nv_bfloat162 h01 = __floats2bfloat162_rn(v.x, v.y);
    __nv_bfloat162 h23 = __floats2bfloat162_rn(v.z, v.w);
    __nv_bfloat162 l01 = __floats2bfloat162_rn(v.x - __low2float(h01),
                                               v.y - __high2float(h01));
    __nv_bfloat162 l23 = __floats2bfloat162_rn(v.z - __low2float(h23),
                                               v.w - __high2float(h23));
    size_t off = (size_t)row * EE + threadIdx.x * 4;
    *(__nv_bfloat162*)(dH + off)     = h01;
    *(__nv_bfloat162*)(dH + off + 2) = h23;
    *(__nv_bfloat162*)(dL + off)     = l01;
    *(__nv_bfloat162*)(dL + off + 2) = l23;
}

// ---------------------------------------------------------------------------
// pool over combined-U (stride NCV), column base cb, exact nsel row-guard
// ---------------------------------------------------------------------------
__global__ void k_pool(const float* __restrict__ U, const float* __restrict__ bc,
                       int kw, int cb, int seg) {
    int b = blockIdx.x;
    int f = threadIdx.x;
    int tlim = TT - kw + 1;
    int ns = g_nsel[b];
    int tcap = ns < tlim ? ns : tlim;
    int t0 = blockIdx.y * 64;
    int t1 = t0 + 64 < tlim ? t0 + 64 : tlim;
    float bcv = bc[f];
    float m = 0.f;
    if (t1 > tcap) m = fmaxf(bcv, 0.f);       // all-zero windows contribute relu(bc)
    int t1c = t1 < tcap ? t1 : tcap;
    const float* Ub = U + (size_t)b * TT * NCV + cb + (size_t)f * kw;
    for (int t = t0; t < t1c; t++) {
        float s = bcv;
        int dtmax = ns - t; if (dtmax > kw) dtmax = kw;
        for (int dt = 0; dt < dtmax; dt++)
            s += Ub[(size_t)(t + dt) * NCV + dt];
        m = fmaxf(m, fmaxf(s, 0.f));
    }
    atomicMax((int*)&g_pooled[b * (3 * NF) + seg + f], __float_as_int(m));
}

// ---------------------------------------------------------------------------
__global__ void k_final(const float* __restrict__ Wo, const float* __restrict__ bo,
                        float* __restrict__ out) {
    __shared__ float redf[256];
    int b = blockIdx.x, tid = threadIdx.x;
    float s = 0.f;
    for (int f = tid; f < 3 * NF; f += 256)
        s += g_pooled[b * (3 * NF) + f] * Wo[f];
    redf[tid] = s;
    __syncthreads();
    for (int o = 128; o; o >>= 1) {
        if (tid < o) redf[tid] += redf[tid + o];
        __syncthreads();
    }
    if (tid == 0) out[b] = redf[0] + bo[0];
}

// ---------------------------------------------------------------------------
extern "C" void kernel_launch(void* const* d_in, const int* in_sizes, int n_in,
                              void* d_out, int out_size) {
    const float* emb   = (const float*)d_in[0];
    const int*   mask  = (const int*)  d_in[1];
    const float* Wih_c = (const float*)d_in[2];
    const float* Whh_c = (const float*)d_in[3];
    const float* bih_c = (const float*)d_in[4];
    const float* bhh_c = (const float*)d_in[5];
    const float* Ws    = (const float*)d_in[6];
    const float* bs    = (const float*)d_in[7];
    const float* Wih0  = (const float*)d_in[8];
    const float* Whh0  = (const float*)d_in[9];
    const float* bih0  = (const float*)d_in[10];
    const float* bhh0  = (const float*)d_in[11];
    const float* Wih1  = (const float*)d_in[12];
    const float* Whh1  = (const float*)d_in[13];
    const float* bih1  = (const float*)d_in[14];
    const float* bhh1  = (const float*)d_in[15];
    const float* Wc3   = (const float*)d_in[16];
    const float* bc3   = (const float*)d_in[17];
    const float* Wc4   = (const float*)d_in[18];
    const float* bc4   = (const float*)d_in[19];
    const float* Wc5   = (const float*)d_in[20];
    const float* bc5   = (const float*)d_in[21];
    const float* Wo    = (const float*)d_in[22];
    const float* bo    = (const float*)d_in[23];
    float* out = (float*)d_out;

    cudaFuncSetAttribute(k_recur_mma, cudaFuncAttributeMaxDynamicSharedMemorySize,
                         MSM_BYTES);
    cudaFuncSetAttribute(k_recur_mma3, cudaFuncAttributeMaxDynamicSharedMemorySize,
                         M3_BYTES);
    cudaFuncSetAttribute(k_bgemm, cudaFuncAttributeMaxDynamicSharedMemorySize,
                         BSM_BYTES);
    cudaFuncSetAttribute(k_bgemm3, cudaFuncAttributeMaxDynamicSharedMemorySize,
                         BSM3_BYTES);

    float *pGi, *pS0, *pU;
    int* pNsel;
    __nv_bfloat16 *pAh, *pAl, *pA3, *pWh, *pWl, *pW3;
    cudaGetSymbolAddress((void**)&pGi,   g_Gi);
    cudaGetSymbolAddress((void**)&pS0,   g_seq0);
    cudaGetSymbolAddress((void**)&pU,    g_U);
    cudaGetSymbolAddress((void**)&pNsel, g_nsel);
    cudaGetSymbolAddress((void**)&pAh,   g_Ah);
    cudaGetSymbolAddress((void**)&pAl,   g_Al);
    cudaGetSymbolAddress((void**)&pA3,   g_A3);
    cudaGetSymbolAddress((void**)&pWh,   g_Wh);
    cudaGetSymbolAddress((void**)&pWl,   g_Wl);
    cudaGetSymbolAddress((void**)&pW3,   g_W3);

    const size_t nAE = (size_t)MALL * EE;

    // ---- selector GRU: 3-plane/6-term bf16 tensor path (near-fp32 exact) ----
    k_split3<<<(int)((nAE + 255)/256), 256>>>(emb, pAh, pAl, pA3, nAE);
    k_split3<<<(G3*EE + 255)/256, 256>>>(Wih_c, pWh, pWl, pW3, (size_t)G3*EE);
    k_bgemm3<<<dim3(G3/128, MALL/128), 256, BSM3_BYTES>>>(
        pGi, pAh, pAl, pA3, pWh, pWl, pW3, bih_c, MALL, G3, EE);
    k_split3<<<(G3*HH + 255)/256, 256>>>(Whh_c, pWh, pWl, pW3, (size_t)G3*HH);
    k_reset<<<256, 256>>>();
    k_recur_mma3<<<NBLK, 512, M3_BYTES>>>(pGi, pS0, pWh, pWl, pW3, bhh_c);
    k_selargmax<<<(BB*TT*32 + 255)/256, 256>>>(pS0, Ws, bs);
    k_fix<<<BB, 32>>>(mask);
    k_gather<<<MALL, EE/4>>>(emb, pAh, pAl);

    // ---- layer 0 ----
    k_split<<<(G3*EE + 255)/256, 256>>>(Wih0, pWh, pWl, (size_t)G3*EE);
    k_bgemm<<<dim3(G3/128, MALL/128), 256, BSM_BYTES>>>(
        pGi, pAh, pAl, pWh, pWl, bih0, MALL, G3, EE, pNsel, 1);
    k_split<<<(G3*HH + 255)/256, 256>>>(Whh0, pWh, pWl, (size_t)G3*HH);
    k_reset<<<256, 256>>>();
    k_recur_mma<<<NBLK, 512, MSM_BYTES>>>(pGi, pAh, pAl, pWh, pWl, bhh0, pNsel);

    // ---- layer 1 ----
    k_split<<<(G3*HH + 255)/256, 256>>>(Wih1, pWh, pWl, (size_t)G3*HH);
    k_bgemm<<<dim3(G3/128, MALL/128), 256, BSM_BYTES>>>(
        pGi, pAh, pAl, pWh, pWl, bih1, MALL, G3, HH, pNsel, 1);
    k_split<<<(G3*HH + 255)/256, 256>>>(Whh1, pWh, pWl, (size_t)G3*HH);
    k_reset<<<256, 256>>>();
    k_recur_mma<<<NBLK, 512, MSM_BYTES>>>(pGi, pAh, pAl, pWh, pWl, bhh1, pNsel);

    // ---- convs: ONE combined bgemm (N=3072) over concatenated weights ----
    k_zero_pooled<<<(BB*3*NF + 255)/256, 256>>>();
    k_split<<<(NF*3*HH + 255)/256, 256>>>(Wc3, pWh, pWl, (size_t)NF*3*HH);
    k_split<<<(NF*4*HH + 255)/256, 256>>>(Wc4, pWh + (size_t)NF*3*HH,
                                          pWl + (size_t)NF*3*HH, (size_t)NF*4*HH);
    k_split<<<(NF*5*HH + 255)/256, 256>>>(Wc5, pWh + (size_t)NF*7*HH,
                                          pWl + (size_t)NF*7*HH, (size_t)NF*5*HH);
    k_bgemm<<<dim3(NCV/128, MALL/128), 256, BSM_BYTES>>>(
        pU, pAh, pAl, pWh, pWl, nullptr, MALL, NCV, HH, pNsel, 1);
    k_pool<<<dim3(BB, 8), NF>>>(pU, bc3, 3, 0,        0);
    k_pool<<<dim3(BB, 8), NF>>>(pU, bc4, 4, NF*3,     NF);
    k_pool<<<dim3(BB, 8), NF>>>(pU, bc5, 5, NF*7,     2*NF);

    // ---- final projection ----
    k_final<<<BB, 256>>>(Wo, bo, out);
}

// round 16
// speedup vs baseline: 1.0404x; 1.0034x over previous
#include <cuda_runtime.h>
#include <cuda_bf16.h>
#include <math.h>
#include <stdint.h>
#include <stddef.h>

typedef unsigned long long u64;

// Problem dims
#define BB    64
#define TT    512
#define EE    768
#define HH    512
#define G3    1536
#define NF    256
#define MALL  (BB*TT)          // 32768
#define NCV   (NF*12)          // 3072 combined conv output cols

#define NBLK      128

// -------- mma recurrence config (2-plane, layers) --------
#define SWS     520
#define MSM_W   0
#define MSM_WL  (48*SWS)
#define MSM_HH  (96*SWS)
#define MSM_HL  (112*SWS)
#define MSM_BF  (128*SWS)
#define MRED_STR 52
#define MSM_BYTES (MSM_BF*2 + 4*16*MRED_STR*4)   // 146432 B

// -------- mma recurrence config (3-plane, selector) --------
#define M3_W1  0
#define M3_W2  (48*SWS)
#define M3_W3  (96*SWS)
#define M3_H1  (144*SWS)
#define M3_H2  (160*SWS)
#define M3_H3  (176*SWS)
#define M3_BF  (192*SWS)
#define M3_BYTES (M3_BF*2 + 4*16*MRED_STR*4)     // 212992 B

// -------- bf16 tensor GEMM config --------
#define SAS   40
#define PLN   (128*SAS)              // plane elems
#define OPSZ  (128*SAS*2)            // plane bytes
#define BSM_BYTES  (8*OPSZ)          // 2-plane: 2 bufs x 4 planes = 81920 B
#define BSM3_BYTES (12*OPSZ)         // 3-plane: 2 bufs x 6 planes = 122880 B

// ----------------- device scratch (statics; no cudaMalloc allowed) ----------
__device__ float g_Gi[(size_t)MALL * G3];
__device__ float g_seq0[(size_t)MALL * HH];    // selector hist (fp32, argmax)
__device__ float g_U[(size_t)MALL * NCV];
__device__ float g_h[2][BB * HH];
__device__ int   g_sel[BB * TT];
__device__ int   g_order[BB * TT];
__device__ int   g_nsel[BB];
__device__ float g_pooled[BB * 3 * NF];
__device__ unsigned g_bar4[4 * 32];
// bf16 split buffers
__device__ __nv_bfloat16 g_Ah[(size_t)MALL * EE];
__device__ __nv_bfloat16 g_Al[(size_t)MALL * EE];
__device__ __nv_bfloat16 g_Wh[(size_t)NCV * HH];
__device__ __nv_bfloat16 g_Wl[(size_t)NCV * HH];
__device__ __nv_bfloat16 g_W3[G3 * EE];

// ----------------------------- sync helpers ---------------------------------
__device__ __forceinline__ unsigned ld_acq(const unsigned* p) {
    unsigned v;
    asm volatile("ld.acquire.gpu.global.u32 %0,[%1];" : "=r"(v) : "l"(p));
    return v;
}
__device__ __forceinline__ void red_rel(unsigned* p) {
    asm volatile("red.release.gpu.global.add.u32 [%0],1;" :: "l"(p));
}
// ----------------------------- mma helpers ----------------------------------
__device__ __forceinline__ void ldm4(unsigned* r, unsigned addr) {
    asm volatile("ldmatrix.sync.aligned.m8n8.x4.shared.b16 {%0,%1,%2,%3}, [%4];"
                 : "=r"(r[0]), "=r"(r[1]), "=r"(r[2]), "=r"(r[3]) : "r"(addr));
}
__device__ __forceinline__ void mma16816(float* c, const unsigned* a,
                                         unsigned b0, unsigned b1) {
    asm volatile("mma.sync.aligned.m16n8k16.row.col.f32.bf16.bf16.f32 "
                 "{%0,%1,%2,%3}, {%4,%5,%6,%7}, {%8,%9}, {%0,%1,%2,%3};"
                 : "+f"(c[0]), "+f"(c[1]), "+f"(c[2]), "+f"(c[3])
                 : "r"(a[0]), "r"(a[1]), "r"(a[2]), "r"(a[3]), "r"(b0), "r"(b1));
}

// ---------------------------------------------------------------------------
__global__ void k_reset() {
    int i = blockIdx.x * blockDim.x + threadIdx.x;
    if (i < 4 * 32) g_bar4[i] = 0u;
    if (i < 2 * BB * HH) ((float*)g_h)[i] = 0.f;
}
__global__ void k_zero_pooled() {
    int i = blockIdx.x * blockDim.x + threadIdx.x;
    if (i < BB * 3 * NF) g_pooled[i] = 0.f;
}
// split fp32 -> 2 bf16 planes
__global__ void k_split(const float* __restrict__ src,
                        __nv_bfloat16* __restrict__ p1,
                        __nv_bfloat16* __restrict__ p2, size_t n) {
    size_t i = (size_t)blockIdx.x * blockDim.x + threadIdx.x;
    if (i >= n) return;
    float x = src[i];
    __nv_bfloat16 h = __float2bfloat16(x);
    p1[i] = h;
    p2[i] = __float2bfloat16(x - __bfloat162float(h));
}
// split fp32 -> 3 bf16 planes (weights only; A split is fused into k_bgemm3)
__global__ void k_split3(const float* __restrict__ src,
                         __nv_bfloat16* __restrict__ p1,
                         __nv_bfloat16* __restrict__ p2,
                         __nv_bfloat16* __restrict__ p3, size_t n) {
    size_t i = (size_t)blockIdx.x * blockDim.x + threadIdx.x;
    if (i >= n) return;
    float x = src[i];
    __nv_bfloat16 h1 = __float2bfloat16(x);
    float r = x - __bfloat162float(h1);
    __nv_bfloat16 h2 = __float2bfloat16(r);
    float r2 = r - __bfloat162float(h2);
    p1[i] = h1;
    p2[i] = h2;
    p3[i] = __float2bfloat16(r2);
}

// ---------------------------------------------------------------------------
// split-bf16 tensor-core GEMM, 2-plane / 3-term (layers + convs)
// mode 0 compute; mode 1 skip all-invalid 128-row tiles (no write).
// ---------------------------------------------------------------------------
__global__ __launch_bounds__(256, 1)
void k_bgemm(float* __restrict__ C,
             const __nv_bfloat16* __restrict__ Ah, const __nv_bfloat16* __restrict__ Al,
             const __nv_bfloat16* __restrict__ Bh, const __nv_bfloat16* __restrict__ Bl,
             const float* __restrict__ bias,
             int M, int N, int K, const int* __restrict__ nsel, int mode) {
    extern __shared__ __nv_bfloat16 sdyn[];
    int tid = threadIdx.x;
    int bm = blockIdx.y * 128;
    int bn = blockIdx.x * 128;

    if (mode != 0) {
        int p0 = bm & 511;
        if (p0 >= nsel[bm >> 9]) return;
    }

    int wid = tid >> 5, lane = tid & 31;
    int m0 = (wid & 3) * 32, n0 = (wid >> 2) * 64;
    unsigned sbase = (unsigned)__cvta_generic_to_shared(sdyn);

    const __nv_bfloat16* gp[4];
    gp[0] = Ah; gp[1] = Al; gp[2] = Bh; gp[3] = Bl;
    int rbase[4] = {bm, bm, bn, bn};
    int id0 = tid * 2, id1 = tid * 2 + 1;
    int row0 = id0 >> 2, seg0 = (id0 & 3) * 8;
    int row1 = id1 >> 2, seg1 = (id1 & 3) * 8;

    float acc[2][8][4];
    #pragma unroll
    for (int i = 0; i < 2; i++)
        #pragma unroll
        for (int j = 0; j < 8; j++)
            #pragma unroll
            for (int c = 0; c < 4; c++) acc[i][j][c] = 0.f;

    uint4 rg[4][2];
    #pragma unroll
    for (int p = 0; p < 4; p++) {
        rg[p][0] = *(const uint4*)(gp[p] + (size_t)(rbase[p] + row0) * K + seg0);
        rg[p][1] = *(const uint4*)(gp[p] + (size_t)(rbase[p] + row1) * K + seg1);
    }
    #pragma unroll
    for (int p = 0; p < 4; p++) {
        __nv_bfloat16* sp = sdyn + (size_t)p * PLN;
        *(uint4*)&sp[row0 * SAS + seg0] = rg[p][0];
        *(uint4*)&sp[row1 * SAS + seg1] = rg[p][1];
    }
    __syncthreads();

    int alr = lane & 15, alh = (lane >> 4) * 16;
    int bro = ((lane >> 4) & 1) * 8 + (lane & 7);
    int bko = ((lane >> 3) & 1) * 16;

    int nslab = K >> 5;
    for (int sl = 0; sl < nslab; sl++) {
        int buf = sl & 1;
        if (sl + 1 < nslab) {
            int k0 = (sl + 1) * 32;
            #pragma unroll
            for (int p = 0; p < 4; p++) {
                rg[p][0] = *(const uint4*)(gp[p] + (size_t)(rbase[p] + row0) * K + k0 + seg0);
                rg[p][1] = *(const uint4*)(gp[p] + (size_t)(rbase[p] + row1) * K + k0 + seg1);
            }
        }
        unsigned base = sbase + (unsigned)buf * (4 * OPSZ);
        #pragma unroll
        for (int kk = 0; kk < 32; kk += 16) {
            unsigned ah[2][4], al[2][4], bh[4][4], bl[4][4];
            #pragma unroll
            for (int i = 0; i < 2; i++) {
                unsigned ra = base + ((m0 + 16 * i + alr) * SAS + kk) * 2 + alh;
                ldm4(ah[i], ra);
                ldm4(al[i], ra + OPSZ);
            }
            #pragma unroll
            for (int g = 0; g < 4; g++) {
                unsigned rb = base + 2 * OPSZ + ((n0 + 16 * g + bro) * SAS + kk) * 2 + bko;
                ldm4(bh[g], rb);
                ldm4(bl[g], rb + OPSZ);
            }
            #pragma unroll
            for (int i = 0; i < 2; i++)
                #pragma unroll
                for (int g = 0; g < 4; g++)
                    #pragma unroll
                    for (int h = 0; h < 2; h++) {
                        int j = 2 * g + h;
                        mma16816(acc[i][j], ah[i], bh[g][2*h], bh[g][2*h + 1]);
                        mma16816(acc[i][j], ah[i], bl[g][2*h], bl[g][2*h + 1]);
                        mma16816(acc[i][j], al[i], bh[g][2*h], bh[g][2*h + 1]);
                    }
        }
        if (sl + 1 < nslab) {
            int nb = buf ^ 1;
            #pragma unroll
            for (int p = 0; p < 4; p++) {
                __nv_bfloat16* sp = sdyn + (size_t)(nb * 4 + p) * PLN;
                *(uint4*)&sp[row0 * SAS + seg0] = rg[p][0];
                *(uint4*)&sp[row1 * SAS + seg1] = rg[p][1];
            }
            __syncthreads();
        }
    }
    #pragma unroll
    for (int i = 0; i < 2; i++) {
        int rA = bm + m0 + 16 * i + (lane >> 2);
        #pragma unroll
        for (int j = 0; j < 8; j++) {
            int col = bn + n0 + 8 * j + 2 * (lane & 3);
            float b0v = 0.f, b1v = 0.f;
            if (bias) { b0v = bias[col]; b1v = bias[col + 1]; }
            *(float2*)(C + (size_t)rA * N + col) =
                make_float2(acc[i][j][0] + b0v, acc[i][j][1] + b1v);
            *(float2*)(C + (size_t)(rA + 8) * N + col) =
                make_float2(acc[i][j][2] + b0v, acc[i][j][3] + b1v);
        }
    }
}

// ---------------------------------------------------------------------------
// split-bf16 GEMM, 3-plane / 6-term (selector): A read as fp32 and split to
// 3 planes IN-KERNEL during smem staging (identical residual-chain math to
// k_split3 -> bit-identical smem contents). B from pre-split weight planes.
// ---------------------------------------------------------------------------
__global__ __launch_bounds__(256, 1)
void k_bgemm3(float* __restrict__ C,
              const float* __restrict__ A,
              const __nv_bfloat16* __restrict__ B1, const __nv_bfloat16* __restrict__ B2,
              const __nv_bfloat16* __restrict__ B3,
              const float* __restrict__ bias, int M, int N, int K) {
    extern __shared__ __nv_bfloat16 sdyn[];
    int tid = threadIdx.x;
    int bm = blockIdx.y * 128;
    int bn = blockIdx.x * 128;
    int wid = tid >> 5, lane = tid & 31;
    int m0 = (wid & 3) * 32, n0 = (wid >> 2) * 64;
    unsigned sbase = (unsigned)__cvta_generic_to_shared(sdyn);

    const __nv_bfloat16* bp[3];
    bp[0] = B1; bp[1] = B2; bp[2] = B3;
    // B staging ids (bf16 uint4 granularity)
    int id0 = tid * 2, id1 = tid * 2 + 1;
    int row0 = id0 >> 2, seg0 = (id0 & 3) * 8;
    int row1 = id1 >> 2, seg1 = (id1 & 3) * 8;
    // A staging ids (fp32 float4 granularity): 128 rows x 8 float4
    int ar[4], ac[4];
    #pragma unroll
    for (int q = 0; q < 4; q++) {
        int id = q * 256 + tid;
        ar[q] = id >> 3;
        ac[q] = (id & 7) * 4;
    }

    float acc[2][8][4];
    #pragma unroll
    for (int i = 0; i < 2; i++)
        #pragma unroll
        for (int j = 0; j < 8; j++)
            #pragma unroll
            for (int c = 0; c < 4; c++) acc[i][j][c] = 0.f;

    float4 raf[4];
    uint4 rgB[3][2];
    #pragma unroll
    for (int q = 0; q < 4; q++)
        raf[q] = *(const float4*)(A + (size_t)(bm + ar[q]) * K + ac[q]);
    #pragma unroll
    for (int p = 0; p < 3; p++) {
        rgB[p][0] = *(const uint4*)(bp[p] + (size_t)(bn + row0) * K + seg0);
        rgB[p][1] = *(const uint4*)(bp[p] + (size_t)(bn + row1) * K + seg1);
    }
    // stage buffer 0
    {
        #pragma unroll
        for (int q = 0; q < 4; q++) {
            float xs[4] = {raf[q].x, raf[q].y, raf[q].z, raf[q].w};
            __nv_bfloat16 h1[4], h2[4], h3[4];
            #pragma unroll
            for (int c = 0; c < 4; c++) {
                h1[c] = __float2bfloat16(xs[c]);
                float r = xs[c] - __bfloat162float(h1[c]);
                h2[c] = __float2bfloat16(r);
                float r2 = r - __bfloat162float(h2[c]);
                h3[c] = __float2bfloat16(r2);
            }
            int off = ar[q] * SAS + ac[q];
            *(uint2*)&sdyn[off]           = *(uint2*)h1;
            *(uint2*)&sdyn[PLN + off]     = *(uint2*)h2;
            *(uint2*)&sdyn[2 * PLN + off] = *(uint2*)h3;
        }
        #pragma unroll
        for (int p = 0; p < 3; p++) {
            __nv_bfloat16* sp = sdyn + (size_t)(3 + p) * PLN;
            *(uint4*)&sp[row0 * SAS + seg0] = rgB[p][0];
            *(uint4*)&sp[row1 * SAS + seg1] = rgB[p][1];
        }
    }
    __syncthreads();

    int alr = lane & 15, alh = (lane >> 4) * 16;
    int bro = ((lane >> 4) & 1) * 8 + (lane & 7);
    int bko = ((lane >> 3) & 1) * 16;

    int nslab = K >> 5;
    for (int sl = 0; sl < nslab; sl++) {
        int buf = sl & 1;
        if (sl + 1 < nslab) {
            int k0 = (sl + 1) * 32;
            #pragma unroll
            for (int q = 0; q < 4; q++)
                raf[q] = *(const float4*)(A + (size_t)(bm + ar[q]) * K + k0 + ac[q]);
            #pragma unroll
            for (int p = 0; p < 3; p++) {
                rgB[p][0] = *(const uint4*)(bp[p] + (size_t)(bn + row0) * K + k0 + seg0);
                rgB[p][1] = *(const uint4*)(bp[p] + (size_t)(bn + row1) * K + k0 + seg1);
            }
        }
        unsigned base = sbase + (unsigned)buf * (6 * OPSZ);
        #pragma unroll
        for (int kk = 0; kk < 32; kk += 16) {
            unsigned a1[2][4], a2[2][4], a3[2][4];
            unsigned b1[4][4], b2[4][4], b3[4][4];
            #pragma unroll
            for (int i = 0; i < 2; i++) {
                unsigned ra = base + ((m0 + 16 * i + alr) * SAS + kk) * 2 + alh;
                ldm4(a1[i], ra);
                ldm4(a2[i], ra + OPSZ);
                ldm4(a3[i], ra + 2 * OPSZ);
            }
            #pragma unroll
            for (int g = 0; g < 4; g++) {
                unsigned rb = base + 3 * OPSZ + ((n0 + 16 * g + bro) * SAS + kk) * 2 + bko;
                ldm4(b1[g], rb);
                ldm4(b2[g], rb + OPSZ);
                ldm4(b3[g], rb + 2 * OPSZ);
            }
            #pragma unroll
            for (int i = 0; i < 2; i++)
                #pragma unroll
                for (int g = 0; g < 4; g++)
                    #pragma unroll
                    for (int h = 0; h < 2; h++) {
                        int j = 2 * g + h;
                        mma16816(acc[i][j], a1[i], b1[g][2*h], b1[g][2*h + 1]);
                        mma16816(acc[i][j], a1[i], b2[g][2*h], b2[g][2*h + 1]);
                        mma16816(acc[i][j], a2[i], b1[g][2*h], b1[g][2*h + 1]);
                        mma16816(acc[i][j], a1[i], b3[g][2*h], b3[g][2*h + 1]);
                        mma16816(acc[i][j], a2[i], b2[g][2*h], b2[g][2*h + 1]);
                        mma16816(acc[i][j], a3[i], b1[g][2*h], b1[g][2*h + 1]);
                    }
        }
        if (sl + 1 < nslab) {
            int nb = buf ^ 1;
            __nv_bfloat16* sd = sdyn + (size_t)nb * (6 * PLN);
            #pragma unroll
            for (int q = 0; q < 4; q++) {
                float xs[4] = {raf[q].x, raf[q].y, raf[q].z, raf[q].w};
                __nv_bfloat16 h1[4], h2[4], h3[4];
                #pragma unroll
                for (int c = 0; c < 4; c++) {
                    h1[c] = __float2bfloat16(xs[c]);
                    float r = xs[c] - __bfloat162float(h1[c]);
                    h2[c] = __float2bfloat16(r);
                    float r2 = r - __bfloat162float(h2[c]);
                    h3[c] = __float2bfloat16(r2);
                }
                int off = ar[q] * SAS + ac[q];
                *(uint2*)&sd[off]           = *(uint2*)h1;
                *(uint2*)&sd[PLN + off]     = *(uint2*)h2;
                *(uint2*)&sd[2 * PLN + off] = *(uint2*)h3;
            }
            #pragma unroll
            for (int p = 0; p < 3; p++) {
                __nv_bfloat16* sp = sd + (size_t)(3 + p) * PLN;
                *(uint4*)&sp[row0 * SAS + seg0] = rgB[p][0];
                *(uint4*)&sp[row1 * SAS + seg1] = rgB[p][1];
            }
            __syncthreads();
        }
    }
    #pragma unroll
    for (int i = 0; i < 2; i++) {
        int rA = bm + m0 + 16 * i + (lane >> 2);
        #pragma unroll
        for (int j = 0; j < 8; j++) {
            int col = bn + n0 + 8 * j + 2 * (lane & 3);
            float b0v = 0.f, b1v = 0.f;
            if (bias) { b0v = bias[col]; b1v = bias[col + 1]; }
            *(float2*)(C + (size_t)rA * N + col) =
                make_float2(acc[i][j][0] + b0v, acc[i][j][1] + b1v);
            *(float2*)(C + (size_t)(rA + 8) * N + col) =
                make_float2(acc[i][j][2] + b0v, acc[i][j][3] + b1v);
        }
    }
}

// ---------------------------------------------------------------------------
// tensor-core GRU recurrence, 2-plane / 3-term (layers 0/1), 512 threads.
// ---------------------------------------------------------------------------
__global__ __launch_bounds__(512, 1)
void k_recur_mma(const float* __restrict__ Gi,
                 __nv_bfloat16* __restrict__ outH, __nv_bfloat16* __restrict__ outL,
                 const __nv_bfloat16* __restrict__ Wh,
                 const __nv_bfloat16* __restrict__ Wl,
                 const float* __restrict__ bhh, const int* __restrict__ nsel) {
    extern __shared__ __nv_bfloat16 smb[];
    float* red = (float*)(smb + MSM_BF);
    int tid = threadIdx.x;
    int bt = blockIdx.x & 3, jt = blockIdx.x >> 2;
    int b0 = bt * 16, j0 = jt * 16;
    int wid = tid >> 5, lane = tid & 31;
    int jj = tid & 15, bb2 = tid >> 4;
    bool ph2 = tid < 256;
    int j2 = j0 + jj;
    int b2 = b0 + (bb2 & 15);

    for (int idx = tid; idx < 48 * 512; idx += 512) {
        int r = idx >> 9, k = idx & 511;
        int g = r >> 4, jl = r & 15;
        size_t grow = (size_t)(g * 512 + j0 + jl) * 512 + k;
        smb[MSM_W  + r * SWS + k] = Wh[grow];
        smb[MSM_WL + r * SWS + k] = Wl[grow];
    }
    float br = bhh[j2], bz = bhh[512 + j2], bn2 = bhh[1024 + j2];
    int lim = ph2 ? nsel[b2] : TT;
    int maxlim = 0;
    #pragma unroll
    for (int b = 0; b < 16; b++) {
        int v = nsel[b0 + b];
        maxlim = v > maxlim ? v : maxlim;
    }
    unsigned* barp = &g_bar4[bt * 32];
    unsigned sbase = (unsigned)__cvta_generic_to_shared(smb);

    int alr = lane & 15, alh = (lane >> 4) * 16;
    int bro = ((lane >> 4) & 1) * 8 + (lane & 7);
    int bko = ((lane >> 3) & 1) * 16;

    __syncthreads();

    for (int t = 0; t < maxlim; t++) {
        float gir = 0.f, giz = 0.f, gin = 0.f;
        if (ph2) {
            const float* gp = Gi + ((size_t)b2 * TT + t) * G3;
            gir = __ldcg(gp + j2);
            giz = __ldcg(gp + 512 + j2);
            gin = __ldcg(gp + 1024 + j2);
        }

        if (t > 0) {
            if (tid == 0) {
                unsigned tgt = 32u * (unsigned)t;
                while (ld_acq(barp) < tgt) { }
            }
            __syncthreads();
        }

        const float* hsrc = g_h[t & 1];
        float hold = 0.f;
        if (ph2) hold = __ldcg(hsrc + (size_t)b2 * HH + j2);
        #pragma unroll
        for (int i = 0; i < 4; i++) {
            int id = tid + i * 512;
            int lb = id >> 7;
            int lk = (id & 127) * 4;
            float4 v = __ldcg((const float4*)(hsrc + (size_t)(b0 + lb) * HH + lk));
            __nv_bfloat162 h01 = __floats2bfloat162_rn(v.x, v.y);
            __nv_bfloat162 h23 = __floats2bfloat162_rn(v.z, v.w);
            __nv_bfloat162 l01 = __floats2bfloat162_rn(v.x - __low2float(h01),
                                                       v.y - __high2float(h01));
            __nv_bfloat162 l23 = __floats2bfloat162_rn(v.z - __low2float(h23),
                                                       v.w - __high2float(h23));
            int off = lb * SWS + lk;
            *(__nv_bfloat162*)&smb[MSM_HH + off]     = h01;
            *(__nv_bfloat162*)&smb[MSM_HH + off + 2] = h23;
            *(__nv_bfloat162*)&smb[MSM_HL + off]     = l01;
            *(__nv_bfloat162*)&smb[MSM_HL + off + 2] = l23;
        }
        __syncthreads();

        if (wid < 12) {
            int gt = wid % 3, kq = wid / 3;
            float acc0[4] = {0.f, 0.f, 0.f, 0.f};
            float acc1[4] = {0.f, 0.f, 0.f, 0.f};
            #pragma unroll
            for (int ks = 0; ks < 8; ks++) {
                int kk = kq * 128 + ks * 16;
                unsigned ah[4], al[4], bh[4], bl[4];
                unsigned ra = sbase + (unsigned)(MSM_HH + alr * SWS + kk) * 2 + alh;
                ldm4(ah, ra);
                ldm4(al, ra + (MSM_HL - MSM_HH) * 2);
                unsigned rb = sbase + (unsigned)((gt * 16 + bro) * SWS + kk) * 2 + bko;
                ldm4(bh, rb);
                ldm4(bl, rb + MSM_WL * 2);
                mma16816(acc0, ah, bh[0], bh[1]);
                mma16816(acc0, ah, bl[0], bl[1]);
                mma16816(acc0, al, bh[0], bh[1]);
                mma16816(acc1, ah, bh[2], bh[3]);
                mma16816(acc1, ah, bl[2], bl[3]);
                mma16816(acc1, al, bh[2], bh[3]);
            }
            int r = lane >> 2, c2 = 2 * (lane & 3);
            float* rp = red + (kq * 16 + r) * MRED_STR + gt * 16;
            *(float2*)(rp + c2)                    = make_float2(acc0[0], acc0[1]);
            *(float2*)(rp + 8 * MRED_STR + c2)     = make_float2(acc0[2], acc0[3]);
            *(float2*)(rp + 8 + c2)                = make_float2(acc1[0], acc1[1]);
            *(float2*)(rp + 8 * MRED_STR + 8 + c2) = make_float2(acc1[2], acc1[3]);
        }
        __syncthreads();

        float y = 0.f;
        if (ph2) {
            float sr = br, sz = bz, sn = bn2;
            #pragma unroll
            for (int kq = 0; kq < 4; kq++) {
                const float* rp = red + (kq * 16 + (bb2 & 15)) * MRED_STR;
                sr += rp[jj];
                sz += rp[16 + jj];
                sn += rp[32 + jj];
            }
            float r_ = 1.f / (1.f + expf(-(gir + sr)));
            float z  = 1.f / (1.f + expf(-(giz + sz)));
            float n  = tanhf(gin + r_ * sn);
            float hn = (1.f - z) * n + z * hold;
            bool valid = t < lim;
            g_h[(t + 1) & 1][b2 * HH + j2] = valid ? hn : hold;
            y = valid ? hn : 0.f;
        }

        __syncthreads();
        if (tid == 0) red_rel(barp);

        if (ph2) {
            __nv_bfloat16 yh = __float2bfloat16(y);
            size_t oidx = ((size_t)b2 * TT + t) * HH + j2;
            outH[oidx] = yh;
            outL[oidx] = __float2bfloat16(y - __bfloat162float(yh));
        }
    }

    if (ph2) {
        __nv_bfloat16 zb = __float2bfloat16(0.f);
        for (int t = maxlim; t < TT; t++) {
            size_t oidx = ((size_t)b2 * TT + t) * HH + j2;
            outH[oidx] = zb;
            outL[oidx] = zb;
        }
    }
}

// ---------------------------------------------------------------------------
// tensor-core GRU recurrence, 3-plane / 6-term (selector), 512 threads.
// ---------------------------------------------------------------------------
__global__ __launch_bounds__(512, 1)
void k_recur_mma3(const float* __restrict__ Gi, float* __restrict__ hist,
                  const __nv_bfloat16* __restrict__ W1,
                  const __nv_bfloat16* __restrict__ W2,
                  const __nv_bfloat16* __restrict__ W3,
                  const float* __restrict__ bhh) {
    extern __shared__ __nv_bfloat16 smb[];
    float* red = (float*)(smb + M3_BF);
    int tid = threadIdx.x;
    int bt = blockIdx.x & 3, jt = blockIdx.x >> 2;
    int b0 = bt * 16, j0 = jt * 16;
    int wid = tid >> 5, lane = tid & 31;
    int jj = tid & 15, bb2 = tid >> 4;
    bool ph2 = tid < 256;
    int j2 = j0 + jj;
    int b2 = b0 + (bb2 & 15);

    for (int idx = tid; idx < 48 * 512; idx += 512) {
        int r = idx >> 9, k = idx & 511;
        int g = r >> 4, jl = r & 15;
        size_t grow = (size_t)(g * 512 + j0 + jl) * 512 + k;
        smb[M3_W1 + r * SWS + k] = W1[grow];
        smb[M3_W2 + r * SWS + k] = W2[grow];
        smb[M3_W3 + r * SWS + k] = W3[grow];
    }
    float br = bhh[j2], bz = bhh[512 + j2], bn2 = bhh[1024 + j2];
    unsigned* barp = &g_bar4[bt * 32];
    unsigned sbase = (unsigned)__cvta_generic_to_shared(smb);

    int alr = lane & 15, alh = (lane >> 4) * 16;
    int bro = ((lane >> 4) & 1) * 8 + (lane & 7);
    int bko = ((lane >> 3) & 1) * 16;

    __syncthreads();

    for (int t = 0; t < TT; t++) {
        float gir = 0.f, giz = 0.f, gin = 0.f;
        if (ph2) {
            const float* gp = Gi + ((size_t)b2 * TT + t) * G3;
            gir = __ldcg(gp + j2);
            giz = __ldcg(gp + 512 + j2);
            gin = __ldcg(gp + 1024 + j2);
        }

        if (t > 0) {
            if (tid == 0) {
                unsigned tgt = 32u * (unsigned)t;
                while (ld_acq(barp) < tgt) { }
            }
            __syncthreads();
        }

        const float* hsrc = g_h[t & 1];
        float hold = 0.f;
        if (ph2) hold = __ldcg(hsrc + (size_t)b2 * HH + j2);
        #pragma unroll
        for (int i = 0; i < 4; i++) {
            int id = tid + i * 512;
            int lb = id >> 7;
            int lk = (id & 127) * 4;
            float4 v = __ldcg((const float4*)(hsrc + (size_t)(b0 + lb) * HH + lk));
            float xs[4] = {v.x, v.y, v.z, v.w};
            __nv_bfloat16 h1[4], h2[4], h3[4];
            #pragma unroll
            for (int c = 0; c < 4; c++) {
                h1[c] = __float2bfloat16(xs[c]);
                float r = xs[c] - __bfloat162float(h1[c]);
                h2[c] = __float2bfloat16(r);
                float r2 = r - __bfloat162float(h2[c]);
                h3[c] = __float2bfloat16(r2);
            }
            int off = lb * SWS + lk;
            *(__nv_bfloat162*)&smb[M3_H1 + off]     = *(__nv_bfloat162*)&h1[0];
            *(__nv_bfloat162*)&smb[M3_H1 + off + 2] = *(__nv_bfloat162*)&h1[2];
            *(__nv_bfloat162*)&smb[M3_H2 + off]     = *(__nv_bfloat162*)&h2[0];
            *(__nv_bfloat162*)&smb[M3_H2 + off + 2] = *(__nv_bfloat162*)&h2[2];
            *(__nv_bfloat162*)&smb[M3_H3 + off]     = *(__nv_bfloat162*)&h3[0];
            *(__nv_bfloat162*)&smb[M3_H3 + off + 2] = *(__nv_bfloat162*)&h3[2];
        }
        __syncthreads();

        if (wid < 12) {
            int gt = wid % 3, kq = wid / 3;
            float acc0[4] = {0.f, 0.f, 0.f, 0.f};
            float acc1[4] = {0.f, 0.f, 0.f, 0.f};
            #pragma unroll
            for (int ks = 0; ks < 8; ks++) {
                int kk = kq * 128 + ks * 16;
                unsigned a1[4], a2[4], a3[4], b1[4], b2[4], b3[4];
                unsigned ra = sbase + (unsigned)(M3_H1 + alr * SWS + kk) * 2 + alh;
                ldm4(a1, ra);
                ldm4(a2, ra + (M3_H2 - M3_H1) * 2);
                ldm4(a3, ra + (M3_H3 - M3_H1) * 2);
                unsigned rb = sbase + (unsigned)((gt * 16 + bro) * SWS + kk) * 2 + bko;
                ldm4(b1, rb);
                ldm4(b2, rb + M3_W2 * 2);
                ldm4(b3, rb + M3_W3 * 2);
                mma16816(acc0, a1, b1[0], b1[1]);
                mma16816(acc0, a1, b2[0], b2[1]);
                mma16816(acc0, a2, b1[0], b1[1]);
                mma16816(acc0, a1, b3[0], b3[1]);
                mma16816(acc0, a2, b2[0], b2[1]);
                mma16816(acc0, a3, b1[0], b1[1]);
                mma16816(acc1, a1, b1[2], b1[3]);
                mma16816(acc1, a1, b2[2], b2[3]);
                mma16816(acc1, a2, b1[2], b1[3]);
                mma16816(acc1, a1, b3[2], b3[3]);
                mma16816(acc1, a2, b2[2], b2[3]);
                mma16816(acc1, a3, b1[2], b1[3]);
            }
            int r = lane >> 2, c2 = 2 * (lane & 3);
            float* rp = red + (kq * 16 + r) * MRED_STR + gt * 16;
            *(float2*)(rp + c2)                    = make_float2(acc0[0], acc0[1]);
            *(float2*)(rp + 8 * MRED_STR + c2)     = make_float2(acc0[2], acc0[3]);
            *(float2*)(rp + 8 + c2)                = make_float2(acc1[0], acc1[1]);
            *(float2*)(rp + 8 * MRED_STR + 8 + c2) = make_float2(acc1[2], acc1[3]);
        }
        __syncthreads();

        float hn = 0.f;
        if (ph2) {
            float sr = br, sz = bz, sn = bn2;
            #pragma unroll
            for (int kq = 0; kq < 4; kq++) {
                const float* rp = red + (kq * 16 + (bb2 & 15)) * MRED_STR;
                sr += rp[jj];
                sz += rp[16 + jj];
                sn += rp[32 + jj];
            }
            float r_ = 1.f / (1.f + expf(-(gir + sr)));
            float z  = 1.f / (1.f + expf(-(giz + sz)));
            float n  = tanhf(gin + r_ * sn);
            hn = (1.f - z) * n + z * hold;
            g_h[(t + 1) & 1][b2 * HH + j2] = hn;
        }

        __syncthreads();
        if (tid == 0) red_rel(barp);

        if (ph2)
            hist[((size_t)b2 * TT + t) * HH + j2] = hn;
    }
}

// ---------------------------------------------------------------------------
__global__ void k_selargmax(const float* __restrict__ hist,
                            const float* __restrict__ Ws,
                            const float* __restrict__ bs) {
    int gw = (blockIdx.x * blockDim.x + threadIdx.x) >> 5;
    int lane = threadIdx.x & 31;
    if (gw >= BB * TT) return;
    const float* h = hist + (size_t)gw * HH;
    float l0 = 0.f, l1 = 0.f;
    #pragma unroll 4
    for (int jv = lane; jv < HH; jv += 32) {
        float hv = h[jv];
        l0 += hv * Ws[jv];
        l1 += hv * Ws[HH + jv];
    }
    #pragma unroll
    for (int o = 16; o; o >>= 1) {
        l0 += __shfl_down_sync(0xffffffffu, l0, o);
        l1 += __shfl_down_sync(0xffffffffu, l1, o);
    }
    if (lane == 0)
        g_sel[gw] = ((l1 + bs[1]) > (l0 + bs[0])) ? 1 : 0;
}

// ---------------------------------------------------------------------------
__global__ void k_fix(const int* __restrict__ mask) {
    int b = blockIdx.x;
    int lane = threadIdx.x;
    int len = 0;
    for (int t = lane; t < TT; t += 32) len += mask[b * TT + t];
    #pragma unroll
    for (int o = 16; o; o >>= 1) len += __shfl_down_sync(0xffffffffu, len, o);
    len = __shfl_sync(0xffffffffu, len, 0);
    int cnt = 0;
    for (int c = 0; c < TT; c += 32) {
        int t = c + lane;
        int s = g_sel[b * TT + t];
        if (t == 0) s = 1;
        if (t == len - 1) s = 1;
        if (t >= len) s = 0;
        unsigned bal = __ballot_sync(0xffffffffu, s);
        int pre = __popc(bal & ((1u << lane) - 1u));
        if (s) g_order[b * TT + cnt + pre] = t;
        cnt += __popc(bal);
    }
    if (lane == 0) g_nsel[b] = cnt;
}

// ---------------------------------------------------------------------------
// gather fused with 2-plane split
// ---------------------------------------------------------------------------
__global__ void k_gather(const float* __restrict__ emb,
                         __nv_bfloat16* __restrict__ dH,
                         __nv_bfloat16* __restrict__ dL) {
    int row = blockIdx.x;               // b*T + p
    int b = row >> 9, p = row & 511;
    float4 v = make_float4(0.f, 0.f, 0.f, 0.f);
    if (p < g_nsel[b]) {
        int t = g_order[row];
        v = ((const float4*)(emb + ((size_t)b * TT + t) * EE))[threadIdx.x];
    }
    __nv_bfloat162 h01 = __floats2bfloat162_rn(v.x, v.y);
    __nv_bfloat162 h23 = __floats2bfloat162_rn(v.z, v.w);
    __nv_bfloat162 l01 = __floats2bfloat162_rn(v.x - __low2float(h01),
                                               v.y - __high2float(h01));
    __nv_bfloat162 l23 = __floats2bfloat162_rn(v.z - __low2float(h23),
                                               v.w - __high2float(h23));
    size_t off = (size_t)row * EE + threadIdx.x * 4;
    *(__nv_bfloat162*)(dH + off)     = h01;
    *(__nv_bfloat162*)(dH + off + 2) = h23;
    *(__nv_bfloat162*)(dL + off)     = l01;
    *(__nv_bfloat162*)(dL + off + 2) = l23;
}

// ---------------------------------------------------------------------------
// pool over combined-U (stride NCV), column base cb, exact nsel row-guard
// ---------------------------------------------------------------------------
__global__ void k_pool(const float* __restrict__ U, const float* __restrict__ bc,
                       int kw, int cb, int seg) {
    int b = blockIdx.x;
    int f = threadIdx.x;
    int tlim = TT - kw + 1;
    int ns = g_nsel[b];
    int tcap = ns < tlim ? ns : tlim;
    int t0 = blockIdx.y * 64;
    int t1 = t0 + 64 < tlim ? t0 + 64 : tlim;
    float bcv = bc[f];
    float m = 0.f;
    if (t1 > tcap) m = fmaxf(bcv, 0.f);
    int t1c = t1 < tcap ? t1 : tcap;
    const float* Ub = U + (size_t)b * TT * NCV + cb + (size_t)f * kw;
    for (int t = t0; t < t1c; t++) {
        float s = bcv;
        int dtmax = ns - t; if (dtmax > kw) dtmax = kw;
        for (int dt = 0; dt < dtmax; dt++)
            s += Ub[(size_t)(t + dt) * NCV + dt];
        m = fmaxf(m, fmaxf(s, 0.f));
    }
    atomicMax((int*)&g_pooled[b * (3 * NF) + seg + f], __float_as_int(m));
}

// ---------------------------------------------------------------------------
__global__ void k_final(const float* __restrict__ Wo, const float* __restrict__ bo,
                        float* __restrict__ out) {
    __shared__ float redf[256];
    int b = blockIdx.x, tid = threadIdx.x;
    float s = 0.f;
    for (int f = tid; f < 3 * NF; f += 256)
        s += g_pooled[b * (3 * NF) + f] * Wo[f];
    redf[tid] = s;
    __syncthreads();
    for (int o = 128; o; o >>= 1) {
        if (tid < o) redf[tid] += redf[tid + o];
        __syncthreads();
    }
    if (tid == 0) out[b] = redf[0] + bo[0];
}

// ---------------------------------------------------------------------------
extern "C" void kernel_launch(void* const* d_in, const int* in_sizes, int n_in,
                              void* d_out, int out_size) {
    const float* emb   = (const float*)d_in[0];
    const int*   mask  = (const int*)  d_in[1];
    const float* Wih_c = (const float*)d_in[2];
    const float* Whh_c = (const float*)d_in[3];
    const float* bih_c = (const float*)d_in[4];
    const float* bhh_c = (const float*)d_in[5];
    const float* Ws    = (const float*)d_in[6];
    const float* bs    = (const float*)d_in[7];
    const float* Wih0  = (const float*)d_in[8];
    const float* Whh0  = (const float*)d_in[9];
    const float* bih0  = (const float*)d_in[10];
    const float* bhh0  = (const float*)d_in[11];
    const float* Wih1  = (const float*)d_in[12];
    const float* Whh1  = (const float*)d_in[13];
    const float* bih1  = (const float*)d_in[14];
    const float* bhh1  = (const float*)d_in[15];
    const float* Wc3   = (const float*)d_in[16];
    const float* bc3   = (const float*)d_in[17];
    const float* Wc4   = (const float*)d_in[18];
    const float* bc4   = (const float*)d_in[19];
    const float* Wc5   = (const float*)d_in[20];
    const float* bc5   = (const float*)d_in[21];
    const float* Wo    = (const float*)d_in[22];
    const float* bo    = (const float*)d_in[23];
    float* out = (float*)d_out;

    cudaFuncSetAttribute(k_recur_mma, cudaFuncAttributeMaxDynamicSharedMemorySize,
                         MSM_BYTES);
    cudaFuncSetAttribute(k_recur_mma3, cudaFuncAttributeMaxDynamicSharedMemorySize,
                         M3_BYTES);
    cudaFuncSetAttribute(k_bgemm, cudaFuncAttributeMaxDynamicSharedMemorySize,
                         BSM_BYTES);
    cudaFuncSetAttribute(k_bgemm3, cudaFuncAttributeMaxDynamicSharedMemorySize,
                         BSM3_BYTES);

    float *pGi, *pS0, *pU;
    int* pNsel;
    __nv_bfloat16 *pAh, *pAl, *pWh, *pWl, *pW3;
    cudaGetSymbolAddress((void**)&pGi,   g_Gi);
    cudaGetSymbolAddress((void**)&pS0,   g_seq0);
    cudaGetSymbolAddress((void**)&pU,    g_U);
    cudaGetSymbolAddress((void**)&pNsel, g_nsel);
    cudaGetSymbolAddress((void**)&pAh,   g_Ah);
    cudaGetSymbolAddress((void**)&pAl,   g_Al);
    cudaGetSymbolAddress((void**)&pWh,   g_Wh);
    cudaGetSymbolAddress((void**)&pWl,   g_Wl);
    cudaGetSymbolAddress((void**)&pW3,   g_W3);

    // ---- selector GRU: 3-plane/6-term; A split fused into the GEMM ----
    k_split3<<<(G3*EE + 255)/256, 256>>>(Wih_c, pWh, pWl, pW3, (size_t)G3*EE);
    k_bgemm3<<<dim3(G3/128, MALL/128), 256, BSM3_BYTES>>>(
        pGi, emb, pWh, pWl, pW3, bih_c, MALL, G3, EE);
    k_split3<<<(G3*HH + 255)/256, 256>>>(Whh_c, pWh, pWl, pW3, (size_t)G3*HH);
    k_reset<<<256, 256>>>();
    k_recur_mma3<<<NBLK, 512, M3_BYTES>>>(pGi, pS0, pWh, pWl, pW3, bhh_c);
    k_selargmax<<<(BB*TT*32 + 255)/256, 256>>>(pS0, Ws, bs);
    k_fix<<<BB, 32>>>(mask);
    k_gather<<<MALL, EE/4>>>(emb, pAh, pAl);

    // ---- layer 0 ----
    k_split<<<(G3*EE + 255)/256, 256>>>(Wih0, pWh, pWl, (size_t)G3*EE);
    k_bgemm<<<dim3(G3/128, MALL/128), 256, BSM_BYTES>>>(
        pGi, pAh, pAl, pWh, pWl, bih0, MALL, G3, EE, pNsel, 1);
    k_split<<<(G3*HH + 255)/256, 256>>>(Whh0, pWh, pWl, (size_t)G3*HH);
    k_reset<<<256, 256>>>();
    k_recur_mma<<<NBLK, 512, MSM_BYTES>>>(pGi, pAh, pAl, pWh, pWl, bhh0, pNsel);

    // ---- layer 1 ----
    k_split<<<(G3*HH + 255)/256, 256>>>(Wih1, pWh, pWl, (size_t)G3*HH);
    k_bgemm<<<dim3(G3/128, MALL/128), 256, BSM_BYTES>>>(
        pGi, pAh, pAl, pWh, pWl, bih1, MALL, G3, HH, pNsel, 1);
    k_split<<<(G3*HH + 255)/256, 256>>>(Whh1, pWh, pWl, (size_t)G3*HH);
    k_reset<<<256, 256>>>();
    k_recur_mma<<<NBLK, 512, MSM_BYTES>>>(pGi, pAh, pAl, pWh, pWl, bhh1, pNsel);

    // ---- convs: ONE combined bgemm (N=3072) over concatenated weights ----
    k_zero_pooled<<<(BB*3*NF + 255)/256, 256>>>();
    k_split<<<(NF*3*HH + 255)/256, 256>>>(Wc3, pWh, pWl, (size_t)NF*3*HH);
    k_split<<<(NF*4*HH + 255)/256, 256>>>(Wc4, pWh + (size_t)NF*3*HH,
                                          pWl + (size_t)NF*3*HH, (size_t)NF*4*HH);
    k_split<<<(NF*5*HH + 255)/256, 256>>>(Wc5, pWh + (size_t)NF*7*HH,
                                          pWl + (size_t)NF*7*HH, (size_t)NF*5*HH);
    k_bgemm<<<dim3(NCV/128, MALL/128), 256, BSM_BYTES>>>(
        pU, pAh, pAl, pWh, pWl, nullptr, MALL, NCV, HH, pNsel, 1);
    k_pool<<<dim3(BB, 8), NF>>>(pU, bc3, 3, 0,    0);
    k_pool<<<dim3(BB, 8), NF>>>(pU, bc4, 4, NF*3, NF);
    k_pool<<<dim3(BB, 8), NF>>>(pU, bc5, 5, NF*7, 2*NF);

    // ---- final projection ----
    k_final<<<BB, 256>>>(Wo, bo, out);
}

// round 17
// speedup vs baseline: 1.0636x; 1.0223x over previous
#include <cuda_runtime.h>
#include <cuda_bf16.h>
#include <math.h>
#include <stdint.h>
#include <stddef.h>

typedef unsigned long long u64;

// Problem dims
#define BB    64
#define TT    512
#define EE    768
#define HH    512
#define G3    1536
#define NF    256
#define MALL  (BB*TT)          // 32768
#define NCV   (NF*12)          // 3072 combined conv output cols

#define NBLK      128

// -------- mma recurrence config (2-plane, layers) --------
#define SWS     520
#define MSM_W   0
#define MSM_WL  (48*SWS)
#define MSM_HH  (96*SWS)
#define MSM_HL  (112*SWS)
#define MSM_BF  (128*SWS)
#define MRED_STR 52
#define MSM_BYTES (MSM_BF*2 + 4*16*MRED_STR*4)   // 146432 B

// -------- mma recurrence config (3-plane, selector) --------
#define M3_W1  0
#define M3_W2  (48*SWS)
#define M3_W3  (96*SWS)
#define M3_H1  (144*SWS)
#define M3_H2  (160*SWS)
#define M3_H3  (176*SWS)
#define M3_BF  (192*SWS)
#define M3_BYTES (M3_BF*2 + 4*16*MRED_STR*4)     // 212992 B

// -------- bf16 tensor GEMM config --------
#define SAS   40
#define PLN   (128*SAS)              // plane elems
#define OPSZ  (128*SAS*2)            // plane bytes
#define BSM_BYTES  (8*OPSZ)          // 2-plane: 2 bufs x 4 planes = 81920 B
#define BSM3_BYTES (12*OPSZ)         // 3-plane: 2 bufs x 6 planes = 122880 B

// ----------------- device scratch (statics; no cudaMalloc allowed) ----------
__device__ float g_Gi[(size_t)MALL * G3];
__device__ float g_seq0[(size_t)MALL * HH];    // selector hist (fp32, argmax)
__device__ float g_U[(size_t)MALL * NCV];
__device__ float g_h[2][BB * HH];
__device__ int   g_sel[BB * TT];
__device__ int   g_order[BB * TT];
__device__ int   g_nsel[BB];
__device__ float g_pooled[BB * 3 * NF];
__device__ unsigned g_bar4[4 * 32];            // monotonic across passes
// bf16 split buffers
__device__ __nv_bfloat16 g_Ah[(size_t)MALL * EE];
__device__ __nv_bfloat16 g_Al[(size_t)MALL * EE];
__device__ __nv_bfloat16 g_Wh[(size_t)NCV * HH];
__device__ __nv_bfloat16 g_Wl[(size_t)NCV * HH];
__device__ __nv_bfloat16 g_W3[G3 * EE];

// ----------------------------- sync helpers ---------------------------------
__device__ __forceinline__ unsigned ld_acq(const unsigned* p) {
    unsigned v;
    asm volatile("ld.acquire.gpu.global.u32 %0,[%1];" : "=r"(v) : "l"(p));
    return v;
}
__device__ __forceinline__ void red_rel(unsigned* p) {
    asm volatile("red.release.gpu.global.add.u32 [%0],1;" :: "l"(p));
}
// ----------------------------- mma helpers ----------------------------------
__device__ __forceinline__ void ldm4(unsigned* r, unsigned addr) {
    asm volatile("ldmatrix.sync.aligned.m8n8.x4.shared.b16 {%0,%1,%2,%3}, [%4];"
                 : "=r"(r[0]), "=r"(r[1]), "=r"(r[2]), "=r"(r[3]) : "r"(addr));
}
__device__ __forceinline__ void mma16816(float* c, const unsigned* a,
                                         unsigned b0, unsigned b1) {
    asm volatile("mma.sync.aligned.m16n8k16.row.col.f32.bf16.bf16.f32 "
                 "{%0,%1,%2,%3}, {%4,%5,%6,%7}, {%8,%9}, {%0,%1,%2,%3};"
                 : "+f"(c[0]), "+f"(c[1]), "+f"(c[2]), "+f"(c[3])
                 : "r"(a[0]), "r"(a[1]), "r"(a[2]), "r"(a[3]), "r"(b0), "r"(b1));
}

// ---------------------------------------------------------------------------
__global__ void k_zero_pooled() {
    int i = blockIdx.x * blockDim.x + threadIdx.x;
    if (i < BB * 3 * NF) g_pooled[i] = 0.f;
}
// split fp32 -> 2 bf16 planes
__global__ void k_split(const float* __restrict__ src,
                        __nv_bfloat16* __restrict__ p1,
                        __nv_bfloat16* __restrict__ p2, size_t n) {
    size_t i = (size_t)blockIdx.x * blockDim.x + threadIdx.x;
    if (i >= n) return;
    float x = src[i];
    __nv_bfloat16 h = __float2bfloat16(x);
    p1[i] = h;
    p2[i] = __float2bfloat16(x - __bfloat162float(h));
}
// split fp32 -> 3 bf16 planes (weights only; A split is fused into k_bgemm3)
__global__ void k_split3(const float* __restrict__ src,
                         __nv_bfloat16* __restrict__ p1,
                         __nv_bfloat16* __restrict__ p2,
                         __nv_bfloat16* __restrict__ p3, size_t n) {
    size_t i = (size_t)blockIdx.x * blockDim.x + threadIdx.x;
    if (i >= n) return;
    float x = src[i];
    __nv_bfloat16 h1 = __float2bfloat16(x);
    float r = x - __bfloat162float(h1);
    __nv_bfloat16 h2 = __float2bfloat16(r);
    float r2 = r - __bfloat162float(h2);
    p1[i] = h1;
    p2[i] = h2;
    p3[i] = __float2bfloat16(r2);
}

// ---------------------------------------------------------------------------
// split-bf16 tensor-core GEMM, 2-plane / 3-term (layers + convs)
// mode 0 compute; mode 1 skip all-invalid 128-row tiles (no write).
// ---------------------------------------------------------------------------
__global__ __launch_bounds__(256, 1)
void k_bgemm(float* __restrict__ C,
             const __nv_bfloat16* __restrict__ Ah, const __nv_bfloat16* __restrict__ Al,
             const __nv_bfloat16* __restrict__ Bh, const __nv_bfloat16* __restrict__ Bl,
             const float* __restrict__ bias,
             int M, int N, int K, const int* __restrict__ nsel, int mode) {
    extern __shared__ __nv_bfloat16 sdyn[];
    int tid = threadIdx.x;
    int bm = blockIdx.y * 128;
    int bn = blockIdx.x * 128;

    if (mode != 0) {
        int p0 = bm & 511;
        if (p0 >= nsel[bm >> 9]) return;
    }

    int wid = tid >> 5, lane = tid & 31;
    int m0 = (wid & 3) * 32, n0 = (wid >> 2) * 64;
    unsigned sbase = (unsigned)__cvta_generic_to_shared(sdyn);

    const __nv_bfloat16* gp[4];
    gp[0] = Ah; gp[1] = Al; gp[2] = Bh; gp[3] = Bl;
    int rbase[4] = {bm, bm, bn, bn};
    int id0 = tid * 2, id1 = tid * 2 + 1;
    int row0 = id0 >> 2, seg0 = (id0 & 3) * 8;
    int row1 = id1 >> 2, seg1 = (id1 & 3) * 8;

    float acc[2][8][4];
    #pragma unroll
    for (int i = 0; i < 2; i++)
        #pragma unroll
        for (int j = 0; j < 8; j++)
            #pragma unroll
            for (int c = 0; c < 4; c++) acc[i][j][c] = 0.f;

    uint4 rg[4][2];
    #pragma unroll
    for (int p = 0; p < 4; p++) {
        rg[p][0] = *(const uint4*)(gp[p] + (size_t)(rbase[p] + row0) * K + seg0);
        rg[p][1] = *(const uint4*)(gp[p] + (size_t)(rbase[p] + row1) * K + seg1);
    }
    #pragma unroll
    for (int p = 0; p < 4; p++) {
        __nv_bfloat16* sp = sdyn + (size_t)p * PLN;
        *(uint4*)&sp[row0 * SAS + seg0] = rg[p][0];
        *(uint4*)&sp[row1 * SAS + seg1] = rg[p][1];
    }
    __syncthreads();

    int alr = lane & 15, alh = (lane >> 4) * 16;
    int bro = ((lane >> 4) & 1) * 8 + (lane & 7);
    int bko = ((lane >> 3) & 1) * 16;

    int nslab = K >> 5;
    for (int sl = 0; sl < nslab; sl++) {
        int buf = sl & 1;
        if (sl + 1 < nslab) {
            int k0 = (sl + 1) * 32;
            #pragma unroll
            for (int p = 0; p < 4; p++) {
                rg[p][0] = *(const uint4*)(gp[p] + (size_t)(rbase[p] + row0) * K + k0 + seg0);
                rg[p][1] = *(const uint4*)(gp[p] + (size_t)(rbase[p] + row1) * K + k0 + seg1);
            }
        }
        unsigned base = sbase + (unsigned)buf * (4 * OPSZ);
        #pragma unroll
        for (int kk = 0; kk < 32; kk += 16) {
            unsigned ah[2][4], al[2][4], bh[4][4], bl[4][4];
            #pragma unroll
            for (int i = 0; i < 2; i++) {
                unsigned ra = base + ((m0 + 16 * i + alr) * SAS + kk) * 2 + alh;
                ldm4(ah[i], ra);
                ldm4(al[i], ra + OPSZ);
            }
            #pragma unroll
            for (int g = 0; g < 4; g++) {
                unsigned rb = base + 2 * OPSZ + ((n0 + 16 * g + bro) * SAS + kk) * 2 + bko;
                ldm4(bh[g], rb);
                ldm4(bl[g], rb + OPSZ);
            }
            #pragma unroll
            for (int i = 0; i < 2; i++)
                #pragma unroll
                for (int g = 0; g < 4; g++)
                    #pragma unroll
                    for (int h = 0; h < 2; h++) {
                        int j = 2 * g + h;
                        mma16816(acc[i][j], ah[i], bh[g][2*h], bh[g][2*h + 1]);
                        mma16816(acc[i][j], ah[i], bl[g][2*h], bl[g][2*h + 1]);
                        mma16816(acc[i][j], al[i], bh[g][2*h], bh[g][2*h + 1]);
                    }
        }
        if (sl + 1 < nslab) {
            int nb = buf ^ 1;
            #pragma unroll
            for (int p = 0; p < 4; p++) {
                __nv_bfloat16* sp = sdyn + (size_t)(nb * 4 + p) * PLN;
                *(uint4*)&sp[row0 * SAS + seg0] = rg[p][0];
                *(uint4*)&sp[row1 * SAS + seg1] = rg[p][1];
            }
            __syncthreads();
        }
    }
    #pragma unroll
    for (int i = 0; i < 2; i++) {
        int rA = bm + m0 + 16 * i + (lane >> 2);
        #pragma unroll
        for (int j = 0; j < 8; j++) {
            int col = bn + n0 + 8 * j + 2 * (lane & 3);
            float b0v = 0.f, b1v = 0.f;
            if (bias) { b0v = bias[col]; b1v = bias[col + 1]; }
            *(float2*)(C + (size_t)rA * N + col) =
                make_float2(acc[i][j][0] + b0v, acc[i][j][1] + b1v);
            *(float2*)(C + (size_t)(rA + 8) * N + col) =
                make_float2(acc[i][j][2] + b0v, acc[i][j][3] + b1v);
        }
    }
}

// ---------------------------------------------------------------------------
// split-bf16 GEMM, 3-plane / 6-term (selector): A read fp32, split in-kernel.
// ---------------------------------------------------------------------------
__global__ __launch_bounds__(256, 1)
void k_bgemm3(float* __restrict__ C,
              const float* __restrict__ A,
              const __nv_bfloat16* __restrict__ B1, const __nv_bfloat16* __restrict__ B2,
              const __nv_bfloat16* __restrict__ B3,
              const float* __restrict__ bias, int M, int N, int K) {
    extern __shared__ __nv_bfloat16 sdyn[];
    int tid = threadIdx.x;
    int bm = blockIdx.y * 128;
    int bn = blockIdx.x * 128;
    int wid = tid >> 5, lane = tid & 31;
    int m0 = (wid & 3) * 32, n0 = (wid >> 2) * 64;
    unsigned sbase = (unsigned)__cvta_generic_to_shared(sdyn);

    const __nv_bfloat16* bp[3];
    bp[0] = B1; bp[1] = B2; bp[2] = B3;
    int id0 = tid * 2, id1 = tid * 2 + 1;
    int row0 = id0 >> 2, seg0 = (id0 & 3) * 8;
    int row1 = id1 >> 2, seg1 = (id1 & 3) * 8;
    int ar[4], ac[4];
    #pragma unroll
    for (int q = 0; q < 4; q++) {
        int id = q * 256 + tid;
        ar[q] = id >> 3;
        ac[q] = (id & 7) * 4;
    }

    float acc[2][8][4];
    #pragma unroll
    for (int i = 0; i < 2; i++)
        #pragma unroll
        for (int j = 0; j < 8; j++)
            #pragma unroll
            for (int c = 0; c < 4; c++) acc[i][j][c] = 0.f;

    float4 raf[4];
    uint4 rgB[3][2];
    #pragma unroll
    for (int q = 0; q < 4; q++)
        raf[q] = *(const float4*)(A + (size_t)(bm + ar[q]) * K + ac[q]);
    #pragma unroll
    for (int p = 0; p < 3; p++) {
        rgB[p][0] = *(const uint4*)(bp[p] + (size_t)(bn + row0) * K + seg0);
        rgB[p][1] = *(const uint4*)(bp[p] + (size_t)(bn + row1) * K + seg1);
    }
    {
        #pragma unroll
        for (int q = 0; q < 4; q++) {
            float xs[4] = {raf[q].x, raf[q].y, raf[q].z, raf[q].w};
            __nv_bfloat16 h1[4], h2[4], h3[4];
            #pragma unroll
            for (int c = 0; c < 4; c++) {
                h1[c] = __float2bfloat16(xs[c]);
                float r = xs[c] - __bfloat162float(h1[c]);
                h2[c] = __float2bfloat16(r);
                float r2 = r - __bfloat162float(h2[c]);
                h3[c] = __float2bfloat16(r2);
            }
            int off = ar[q] * SAS + ac[q];
            *(uint2*)&sdyn[off]           = *(uint2*)h1;
            *(uint2*)&sdyn[PLN + off]     = *(uint2*)h2;
            *(uint2*)&sdyn[2 * PLN + off] = *(uint2*)h3;
        }
        #pragma unroll
        for (int p = 0; p < 3; p++) {
            __nv_bfloat16* sp = sdyn + (size_t)(3 + p) * PLN;
            *(uint4*)&sp[row0 * SAS + seg0] = rgB[p][0];
            *(uint4*)&sp[row1 * SAS + seg1] = rgB[p][1];
        }
    }
    __syncthreads();

    int alr = lane & 15, alh = (lane >> 4) * 16;
    int bro = ((lane >> 4) & 1) * 8 + (lane & 7);
    int bko = ((lane >> 3) & 1) * 16;

    int nslab = K >> 5;
    for (int sl = 0; sl < nslab; sl++) {
        int buf = sl & 1;
        if (sl + 1 < nslab) {
            int k0 = (sl + 1) * 32;
            #pragma unroll
            for (int q = 0; q < 4; q++)
                raf[q] = *(const float4*)(A + (size_t)(bm + ar[q]) * K + k0 + ac[q]);
            #pragma unroll
            for (int p = 0; p < 3; p++) {
                rgB[p][0] = *(const uint4*)(bp[p] + (size_t)(bn + row0) * K + k0 + seg0);
                rgB[p][1] = *(const uint4*)(bp[p] + (size_t)(bn + row1) * K + k0 + seg1);
            }
        }
        unsigned base = sbase + (unsigned)buf * (6 * OPSZ);
        #pragma unroll
        for (int kk = 0; kk < 32; kk += 16) {
            unsigned a1[2][4], a2[2][4], a3[2][4];
            unsigned b1[4][4], b2[4][4], b3[4][4];
            #pragma unroll
            for (int i = 0; i < 2; i++) {
                unsigned ra = base + ((m0 + 16 * i + alr) * SAS + kk) * 2 + alh;
                ldm4(a1[i], ra);
                ldm4(a2[i], ra + OPSZ);
                ldm4(a3[i], ra + 2 * OPSZ);
            }
            #pragma unroll
            for (int g = 0; g < 4; g++) {
                unsigned rb = base + 3 * OPSZ + ((n0 + 16 * g + bro) * SAS + kk) * 2 + bko;
                ldm4(b1[g], rb);
                ldm4(b2[g], rb + OPSZ);
                ldm4(b3[g], rb + 2 * OPSZ);
            }
            #pragma unroll
            for (int i = 0; i < 2; i++)
                #pragma unroll
                for (int g = 0; g < 4; g++)
                    #pragma unroll
                    for (int h = 0; h < 2; h++) {
                        int j = 2 * g + h;
                        mma16816(acc[i][j], a1[i], b1[g][2*h], b1[g][2*h + 1]);
                        mma16816(acc[i][j], a1[i], b2[g][2*h], b2[g][2*h + 1]);
                        mma16816(acc[i][j], a2[i], b1[g][2*h], b1[g][2*h + 1]);
                        mma16816(acc[i][j], a1[i], b3[g][2*h], b3[g][2*h + 1]);
                        mma16816(acc[i][j], a2[i], b2[g][2*h], b2[g][2*h + 1]);
                        mma16816(acc[i][j], a3[i], b1[g][2*h], b1[g][2*h + 1]);
                    }
        }
        if (sl + 1 < nslab) {
            int nb = buf ^ 1;
            __nv_bfloat16* sd = sdyn + (size_t)nb * (6 * PLN);
            #pragma unroll
            for (int q = 0; q < 4; q++) {
                float xs[4] = {raf[q].x, raf[q].y, raf[q].z, raf[q].w};
                __nv_bfloat16 h1[4], h2[4], h3[4];
                #pragma unroll
                for (int c = 0; c < 4; c++) {
                    h1[c] = __float2bfloat16(xs[c]);
                    float r = xs[c] - __bfloat162float(h1[c]);
                    h2[c] = __float2bfloat16(r);
                    float r2 = r - __bfloat162float(h2[c]);
                    h3[c] = __float2bfloat16(r2);
                }
                int off = ar[q] * SAS + ac[q];
                *(uint2*)&sd[off]           = *(uint2*)h1;
                *(uint2*)&sd[PLN + off]     = *(uint2*)h2;
                *(uint2*)&sd[2 * PLN + off] = *(uint2*)h3;
            }
            #pragma unroll
            for (int p = 0; p < 3; p++) {
                __nv_bfloat16* sp = sd + (size_t)(3 + p) * PLN;
                *(uint4*)&sp[row0 * SAS + seg0] = rgB[p][0];
                *(uint4*)&sp[row1 * SAS + seg1] = rgB[p][1];
            }
            __syncthreads();
        }
    }
    #pragma unroll
    for (int i = 0; i < 2; i++) {
        int rA = bm + m0 + 16 * i + (lane >> 2);
        #pragma unroll
        for (int j = 0; j < 8; j++) {
            int col = bn + n0 + 8 * j + 2 * (lane & 3);
            float b0v = 0.f, b1v = 0.f;
            if (bias) { b0v = bias[col]; b1v = bias[col + 1]; }
            *(float2*)(C + (size_t)rA * N + col) =
                make_float2(acc[i][j][0] + b0v, acc[i][j][1] + b1v);
            *(float2*)(C + (size_t)(rA + 8) * N + col) =
                make_float2(acc[i][j][2] + b0v, acc[i][j][3] + b1v);
        }
    }
}

// ---------------------------------------------------------------------------
// tensor-core GRU recurrence, 2-plane / 3-term (layers 0/1), 512 threads.
// W mma-fragments HOISTED into registers (loop-invariant). Monotonic barrier
// base read at entry; t==0 uses zero h fast-path (no g_h pre-zeroing).
// ---------------------------------------------------------------------------
__global__ __launch_bounds__(512, 1)
void k_recur_mma(const float* __restrict__ Gi,
                 __nv_bfloat16* __restrict__ outH, __nv_bfloat16* __restrict__ outL,
                 const __nv_bfloat16* __restrict__ Wh,
                 const __nv_bfloat16* __restrict__ Wl,
                 const float* __restrict__ bhh, const int* __restrict__ nsel) {
    extern __shared__ __nv_bfloat16 smb[];
    float* red = (float*)(smb + MSM_BF);
    int tid = threadIdx.x;
    int bt = blockIdx.x & 3, jt = blockIdx.x >> 2;
    int b0 = bt * 16, j0 = jt * 16;
    int wid = tid >> 5, lane = tid & 31;
    int jj = tid & 15, bb2 = tid >> 4;
    bool ph2 = tid < 256;
    int j2 = j0 + jj;
    int b2 = b0 + (bb2 & 15);

    for (int idx = tid; idx < 48 * 512; idx += 512) {
        int r = idx >> 9, k = idx & 511;
        int g = r >> 4, jl = r & 15;
        size_t grow = (size_t)(g * 512 + j0 + jl) * 512 + k;
        smb[MSM_W  + r * SWS + k] = Wh[grow];
        smb[MSM_WL + r * SWS + k] = Wl[grow];
    }
    float br = bhh[j2], bz = bhh[512 + j2], bn2 = bhh[1024 + j2];
    int lim = ph2 ? nsel[b2] : TT;
    int maxlim = 0;
    #pragma unroll
    for (int b = 0; b < 16; b++) {
        int v = nsel[b0 + b];
        maxlim = v > maxlim ? v : maxlim;
    }
    unsigned* barp = &g_bar4[bt * 32];
    unsigned bar_base = ld_acq(barp);   // uniform: previous kernel retired
    unsigned sbase = (unsigned)__cvta_generic_to_shared(smb);

    int alr = lane & 15, alh = (lane >> 4) * 16;
    int bro = ((lane >> 4) & 1) * 8 + (lane & 7);
    int bko = ((lane >> 3) & 1) * 16;
    int gt = wid % 3, kq = wid / 3;

    __syncthreads();

    // hoist loop-invariant W fragments into registers
    unsigned bhW[8][4], blW[8][4];
    if (wid < 12) {
        #pragma unroll
        for (int ks = 0; ks < 8; ks++) {
            int kk = kq * 128 + ks * 16;
            unsigned rb = sbase + (unsigned)((gt * 16 + bro) * SWS + kk) * 2 + bko;
            ldm4(bhW[ks], rb);
            ldm4(blW[ks], rb + MSM_WL * 2);
        }
    }

    for (int t = 0; t < maxlim; t++) {
        float gir = 0.f, giz = 0.f, gin = 0.f;
        if (ph2) {
            const float* gp = Gi + ((size_t)b2 * TT + t) * G3;
            gir = __ldcg(gp + j2);
            giz = __ldcg(gp + 512 + j2);
            gin = __ldcg(gp + 1024 + j2);
        }

        if (t > 0) {
            if (tid == 0) {
                unsigned tgt = bar_base + 32u * (unsigned)t;
                while (ld_acq(barp) < tgt) { }
            }
            __syncthreads();
        }

        float hold = 0.f;
        if (t == 0) {
            // zero h fast-path (h(0) == 0 exactly)
            #pragma unroll
            for (int i = 0; i < 4; i++) {
                int id = tid + i * 512;
                int lb = id >> 7;
                int lk = (id & 127) * 4;
                int off = lb * SWS + lk;
                *(float2*)&smb[MSM_HH + off] = make_float2(0.f, 0.f);
                *(float2*)&smb[MSM_HL + off] = make_float2(0.f, 0.f);
            }
        } else {
            const float* hsrc = g_h[t & 1];
            if (ph2) hold = __ldcg(hsrc + (size_t)b2 * HH + j2);
            #pragma unroll
            for (int i = 0; i < 4; i++) {
                int id = tid + i * 512;
                int lb = id >> 7;
                int lk = (id & 127) * 4;
                float4 v = __ldcg((const float4*)(hsrc + (size_t)(b0 + lb) * HH + lk));
                __nv_bfloat162 h01 = __floats2bfloat162_rn(v.x, v.y);
                __nv_bfloat162 h23 = __floats2bfloat162_rn(v.z, v.w);
                __nv_bfloat162 l01 = __floats2bfloat162_rn(v.x - __low2float(h01),
                                                           v.y - __high2float(h01));
                __nv_bfloat162 l23 = __floats2bfloat162_rn(v.z - __low2float(h23),
                                                           v.w - __high2float(h23));
                int off = lb * SWS + lk;
                *(__nv_bfloat162*)&smb[MSM_HH + off]     = h01;
                *(__nv_bfloat162*)&smb[MSM_HH + off + 2] = h23;
                *(__nv_bfloat162*)&smb[MSM_HL + off]     = l01;
                *(__nv_bfloat162*)&smb[MSM_HL + off + 2] = l23;
            }
        }
        __syncthreads();

        if (wid < 12) {
            float acc0[4] = {0.f, 0.f, 0.f, 0.f};
            float acc1[4] = {0.f, 0.f, 0.f, 0.f};
            #pragma unroll
            for (int ks = 0; ks < 8; ks++) {
                int kk = kq * 128 + ks * 16;
                unsigned ah[4], al[4];
                unsigned ra = sbase + (unsigned)(MSM_HH + alr * SWS + kk) * 2 + alh;
                ldm4(ah, ra);
                ldm4(al, ra + (MSM_HL - MSM_HH) * 2);
                mma16816(acc0, ah, bhW[ks][0], bhW[ks][1]);
                mma16816(acc0, ah, blW[ks][0], blW[ks][1]);
                mma16816(acc0, al, bhW[ks][0], bhW[ks][1]);
                mma16816(acc1, ah, bhW[ks][2], bhW[ks][3]);
                mma16816(acc1, ah, blW[ks][2], blW[ks][3]);
                mma16816(acc1, al, bhW[ks][2], bhW[ks][3]);
            }
            int r = lane >> 2, c2 = 2 * (lane & 3);
            float* rp = red + (kq * 16 + r) * MRED_STR + gt * 16;
            *(float2*)(rp + c2)                    = make_float2(acc0[0], acc0[1]);
            *(float2*)(rp + 8 * MRED_STR + c2)     = make_float2(acc0[2], acc0[3]);
            *(float2*)(rp + 8 + c2)                = make_float2(acc1[0], acc1[1]);
            *(float2*)(rp + 8 * MRED_STR + 8 + c2) = make_float2(acc1[2], acc1[3]);
        }
        __syncthreads();

        float y = 0.f;
        if (ph2) {
            float sr = br, sz = bz, sn = bn2;
            #pragma unroll
            for (int q = 0; q < 4; q++) {
                const float* rp = red + (q * 16 + (bb2 & 15)) * MRED_STR;
                sr += rp[jj];
                sz += rp[16 + jj];
                sn += rp[32 + jj];
            }
            float r_ = 1.f / (1.f + expf(-(gir + sr)));
            float z  = 1.f / (1.f + expf(-(giz + sz)));
            float n  = tanhf(gin + r_ * sn);
            float hn = (1.f - z) * n + z * hold;
            bool valid = t < lim;
            g_h[(t + 1) & 1][b2 * HH + j2] = valid ? hn : hold;
            y = valid ? hn : 0.f;
        }

        __syncthreads();
        if (tid == 0) red_rel(barp);

        if (ph2) {
            __nv_bfloat16 yh = __float2bfloat16(y);
            size_t oidx = ((size_t)b2 * TT + t) * HH + j2;
            outH[oidx] = yh;
            outL[oidx] = __float2bfloat16(y - __bfloat162float(yh));
        }
    }

    if (ph2) {
        __nv_bfloat16 zb = __float2bfloat16(0.f);
        for (int t = maxlim; t < TT; t++) {
            size_t oidx = ((size_t)b2 * TT + t) * HH + j2;
            outH[oidx] = zb;
            outL[oidx] = zb;
        }
    }
}

// ---------------------------------------------------------------------------
// tensor-core GRU recurrence, 3-plane / 6-term (selector), 512 threads.
// Monotonic barrier base; t==0 zero fast-path.
// ---------------------------------------------------------------------------
__global__ __launch_bounds__(512, 1)
void k_recur_mma3(const float* __restrict__ Gi, float* __restrict__ hist,
                  const __nv_bfloat16* __restrict__ W1,
                  const __nv_bfloat16* __restrict__ W2,
                  const __nv_bfloat16* __restrict__ W3,
                  const float* __restrict__ bhh) {
    extern __shared__ __nv_bfloat16 smb[];
    float* red = (float*)(smb + M3_BF);
    int tid = threadIdx.x;
    int bt = blockIdx.x & 3, jt = blockIdx.x >> 2;
    int b0 = bt * 16, j0 = jt * 16;
    int wid = tid >> 5, lane = tid & 31;
    int jj = tid & 15, bb2 = tid >> 4;
    bool ph2 = tid < 256;
    int j2 = j0 + jj;
    int b2 = b0 + (bb2 & 15);

    for (int idx = tid; idx < 48 * 512; idx += 512) {
        int r = idx >> 9, k = idx & 511;
        int g = r >> 4, jl = r & 15;
        size_t grow = (size_t)(g * 512 + j0 + jl) * 512 + k;
        smb[M3_W1 + r * SWS + k] = W1[grow];
        smb[M3_W2 + r * SWS + k] = W2[grow];
        smb[M3_W3 + r * SWS + k] = W3[grow];
    }
    float br = bhh[j2], bz = bhh[512 + j2], bn2 = bhh[1024 + j2];
    unsigned* barp = &g_bar4[bt * 32];
    unsigned bar_base = ld_acq(barp);
    unsigned sbase = (unsigned)__cvta_generic_to_shared(smb);

    int alr = lane & 15, alh = (lane >> 4) * 16;
    int bro = ((lane >> 4) & 1) * 8 + (lane & 7);
    int bko = ((lane >> 3) & 1) * 16;
    int gt = wid % 3, kq = wid / 3;

    __syncthreads();

    for (int t = 0; t < TT; t++) {
        float gir = 0.f, giz = 0.f, gin = 0.f;
        if (ph2) {
            const float* gp = Gi + ((size_t)b2 * TT + t) * G3;
            gir = __ldcg(gp + j2);
            giz = __ldcg(gp + 512 + j2);
            gin = __ldcg(gp + 1024 + j2);
        }

        if (t > 0) {
            if (tid == 0) {
                unsigned tgt = bar_base + 32u * (unsigned)t;
                while (ld_acq(barp) < tgt) { }
            }
            __syncthreads();
        }

        float hold = 0.f;
        if (t == 0) {
            #pragma unroll
            for (int i = 0; i < 4; i++) {
                int id = tid + i * 512;
                int lb = id >> 7;
                int lk = (id & 127) * 4;
                int off = lb * SWS + lk;
                *(float2*)&smb[M3_H1 + off] = make_float2(0.f, 0.f);
                *(float2*)&smb[M3_H2 + off] = make_float2(0.f, 0.f);
                *(float2*)&smb[M3_H3 + off] = make_float2(0.f, 0.f);
            }
        } else {
            const float* hsrc = g_h[t & 1];
            if (ph2) hold = __ldcg(hsrc + (size_t)b2 * HH + j2);
            #pragma unroll
            for (int i = 0; i < 4; i++) {
                int id = tid + i * 512;
                int lb = id >> 7;
                int lk = (id & 127) * 4;
                float4 v = __ldcg((const float4*)(hsrc + (size_t)(b0 + lb) * HH + lk));
                float xs[4] = {v.x, v.y, v.z, v.w};
                __nv_bfloat16 h1[4], h2[4], h3[4];
                #pragma unroll
                for (int c = 0; c < 4; c++) {
                    h1[c] = __float2bfloat16(xs[c]);
                    float r = xs[c] - __bfloat162float(h1[c]);
                    h2[c] = __float2bfloat16(r);
                    float r2 = r - __bfloat162float(h2[c]);
                    h3[c] = __float2bfloat16(r2);
                }
                int off = lb * SWS + lk;
                *(__nv_bfloat162*)&smb[M3_H1 + off]     = *(__nv_bfloat162*)&h1[0];
                *(__nv_bfloat162*)&smb[M3_H1 + off + 2] = *(__nv_bfloat162*)&h1[2];
                *(__nv_bfloat162*)&smb[M3_H2 + off]     = *(__nv_bfloat162*)&h2[0];
                *(__nv_bfloat162*)&smb[M3_H2 + off + 2] = *(__nv_bfloat162*)&h2[2];
                *(__nv_bfloat162*)&smb[M3_H3 + off]     = *(__nv_bfloat162*)&h3[0];
                *(__nv_bfloat162*)&smb[M3_H3 + off + 2] = *(__nv_bfloat162*)&h3[2];
            }
        }
        __syncthreads();

        if (wid < 12) {
            float acc0[4] = {0.f, 0.f, 0.f, 0.f};
            float acc1[4] = {0.f, 0.f, 0.f, 0.f};
            #pragma unroll
            for (int ks = 0; ks < 8; ks++) {
                int kk = kq * 128 + ks * 16;
                unsigned a1[4], a2[4], a3[4], b1[4], b2[4], b3[4];
                unsigned ra = sbase + (unsigned)(M3_H1 + alr * SWS + kk) * 2 + alh;
                ldm4(a1, ra);
                ldm4(a2, ra + (M3_H2 - M3_H1) * 2);
                ldm4(a3, ra + (M3_H3 - M3_H1) * 2);
                unsigned rb = sbase + (unsigned)((gt * 16 + bro) * SWS + kk) * 2 + bko;
                ldm4(b1, rb);
                ldm4(b2, rb + M3_W2 * 2);
                ldm4(b3, rb + M3_W3 * 2);
                mma16816(acc0, a1, b1[0], b1[1]);
                mma16816(acc0, a1, b2[0], b2[1]);
                mma16816(acc0, a2, b1[0], b1[1]);
                mma16816(acc0, a1, b3[0], b3[1]);
                mma16816(acc0, a2, b2[0], b2[1]);
                mma16816(acc0, a3, b1[0], b1[1]);
                mma16816(acc1, a1, b1[2], b1[3]);
                mma16816(acc1, a1, b2[2], b2[3]);
                mma16816(acc1, a2, b1[2], b1[3]);
                mma16816(acc1, a1, b3[2], b3[3]);
                mma16816(acc1, a2, b2[2], b2[3]);
                mma16816(acc1, a3, b1[2], b1[3]);
            }
            int r = lane >> 2, c2 = 2 * (lane & 3);
            float* rp = red + (kq * 16 + r) * MRED_STR + gt * 16;
            *(float2*)(rp + c2)                    = make_float2(acc0[0], acc0[1]);
            *(float2*)(rp + 8 * MRED_STR + c2)     = make_float2(acc0[2], acc0[3]);
            *(float2*)(rp + 8 + c2)                = make_float2(acc1[0], acc1[1]);
            *(float2*)(rp + 8 * MRED_STR + 8 + c2) = make_float2(acc1[2], acc1[3]);
        }
        __syncthreads();

        float hn = 0.f;
        if (ph2) {
            float sr = br, sz = bz, sn = bn2;
            #pragma unroll
            for (int q = 0; q < 4; q++) {
                const float* rp = red + (q * 16 + (bb2 & 15)) * MRED_STR;
                sr += rp[jj];
                sz += rp[16 + jj];
                sn += rp[32 + jj];
            }
            float r_ = 1.f / (1.f + expf(-(gir + sr)));
            float z  = 1.f / (1.f + expf(-(giz + sz)));
            float n  = tanhf(gin + r_ * sn);
            hn = (1.f - z) * n + z * hold;
            g_h[(t + 1) & 1][b2 * HH + j2] = hn;
        }

        __syncthreads();
        if (tid == 0) red_rel(barp);

        if (ph2)
            hist[((size_t)b2 * TT + t) * HH + j2] = hn;
    }
}

// ---------------------------------------------------------------------------
__global__ void k_selargmax(const float* __restrict__ hist,
                            const float* __restrict__ Ws,
                            const float* __restrict__ bs) {
    int gw = (blockIdx.x * blockDim.x + threadIdx.x) >> 5;
    int lane = threadIdx.x & 31;
    if (gw >= BB * TT) return;
    const float* h = hist + (size_t)gw * HH;
    float l0 = 0.f, l1 = 0.f;
    #pragma unroll 4
    for (int jv = lane; jv < HH; jv += 32) {
        float hv = h[jv];
        l0 += hv * Ws[jv];
        l1 += hv * Ws[HH + jv];
    }
    #pragma unroll
    for (int o = 16; o; o >>= 1) {
        l0 += __shfl_down_sync(0xffffffffu, l0, o);
        l1 += __shfl_down_sync(0xffffffffu, l1, o);
    }
    if (lane == 0)
        g_sel[gw] = ((l1 + bs[1]) > (l0 + bs[0])) ? 1 : 0;
}

// ---------------------------------------------------------------------------
__global__ void k_fix(const int* __restrict__ mask) {
    int b = blockIdx.x;
    int lane = threadIdx.x;
    int len = 0;
    for (int t = lane; t < TT; t += 32) len += mask[b * TT + t];
    #pragma unroll
    for (int o = 16; o; o >>= 1) len += __shfl_down_sync(0xffffffffu, len, o);
    len = __shfl_sync(0xffffffffu, len, 0);
    int cnt = 0;
    for (int c = 0; c < TT; c += 32) {
        int t = c + lane;
        int s = g_sel[b * TT + t];
        if (t == 0) s = 1;
        if (t == len - 1) s = 1;
        if (t >= len) s = 0;
        unsigned bal = __ballot_sync(0xffffffffu, s);
        int pre = __popc(bal & ((1u << lane) - 1u));
        if (s) g_order[b * TT + cnt + pre] = t;
        cnt += __popc(bal);
    }
    if (lane == 0) g_nsel[b] = cnt;
}

// ---------------------------------------------------------------------------
// gather fused with 2-plane split
// ---------------------------------------------------------------------------
__global__ void k_gather(const float* __restrict__ emb,
                         __nv_bfloat16* __restrict__ dH,
                         __nv_bfloat16* __restrict__ dL) {
    int row = blockIdx.x;               // b*T + p
    int b = row >> 9, p = row & 511;
    float4 v = make_float4(0.f, 0.f, 0.f, 0.f);
    if (p < g_nsel[b]) {
        int t = g_order[row];
        v = ((const float4*)(emb + ((size_t)b * TT + t) * EE))[threadIdx.x];
    }
    __nv_bfloat162 h01 = __floats2bfloat162_rn(v.x, v.y);
    __nv_bfloat162 h23 = __floats2bfloat162_rn(v.z, v.w);
    __nv_bfloat162 l01 = __floats2bfloat162_rn(v.x - __low2float(h01),
                                               v.y - __high2float(h01));
    __nv_bfloat162 l23 = __floats2bfloat162_rn(v.z - __low2float(h23),
                                               v.w - __high2float(h23));
    size_t off = (size_t)row * EE + threadIdx.x * 4;
    *(__nv_bfloat162*)(dH + off)     = h01;
    *(__nv_bfloat162*)(dH + off + 2) = h23;
    *(__nv_bfloat162*)(dL + off)     = l01;
    *(__nv_bfloat162*)(dL + off + 2) = l23;
}

// ---------------------------------------------------------------------------
// pool over combined-U (stride NCV), column base cb, exact nsel row-guard
// ---------------------------------------------------------------------------
__global__ void k_pool(const float* __restrict__ U, const float* __restrict__ bc,
                       int kw, int cb, int seg) {
    int b = blockIdx.x;
    int f = threadIdx.x;
    int tlim = TT - kw + 1;
    int ns = g_nsel[b];
    int tcap = ns < tlim ? ns : tlim;
    int t0 = blockIdx.y * 64;
    int t1 = t0 + 64 < tlim ? t0 + 64 : tlim;
    float bcv = bc[f];
    float m = 0.f;
    if (t1 > tcap) m = fmaxf(bcv, 0.f);
    int t1c = t1 < tcap ? t1 : tcap;
    const float* Ub = U + (size_t)b * TT * NCV + cb + (size_t)f * kw;
    for (int t = t0; t < t1c; t++) {
        float s = bcv;
        int dtmax = ns - t; if (dtmax > kw) dtmax = kw;
        for (int dt = 0; dt < dtmax; dt++)
            s += Ub[(size_t)(t + dt) * NCV + dt];
        m = fmaxf(m, fmaxf(s, 0.f));
    }
    atomicMax((int*)&g_pooled[b * (3 * NF) + seg + f], __float_as_int(m));
}

// ---------------------------------------------------------------------------
__global__ void k_final(const float* __restrict__ Wo, const float* __restrict__ bo,
                        float* __restrict__ out) {
    __shared__ float redf[256];
    int b = blockIdx.x, tid = threadIdx.x;
    float s = 0.f;
    for (int f = tid; f < 3 * NF; f += 256)
        s += g_pooled[b * (3 * NF) + f] * Wo[f];
    redf[tid] = s;
    __syncthreads();
    for (int o = 128; o; o >>= 1) {
        if (tid < o) redf[tid] += redf[tid + o];
        __syncthreads();
    }
    if (tid == 0) out[b] = redf[0] + bo[0];
}

// ---------------------------------------------------------------------------
extern "C" void kernel_launch(void* const* d_in, const int* in_sizes, int n_in,
                              void* d_out, int out_size) {
    const float* emb   = (const float*)d_in[0];
    const int*   mask  = (const int*)  d_in[1];
    const float* Wih_c = (const float*)d_in[2];
    const float* Whh_c = (const float*)d_in[3];
    const float* bih_c = (const float*)d_in[4];
    const float* bhh_c = (const float*)d_in[5];
    const float* Ws    = (const float*)d_in[6];
    const float* bs    = (const float*)d_in[7];
    const float* Wih0  = (const float*)d_in[8];
    const float* Whh0  = (const float*)d_in[9];
    const float* bih0  = (const float*)d_in[10];
    const float* bhh0  = (const float*)d_in[11];
    const float* Wih1  = (const float*)d_in[12];
    const float* Whh1  = (const float*)d_in[13];
    const float* bih1  = (const float*)d_in[14];
    const float* bhh1  = (const float*)d_in[15];
    const float* Wc3   = (const float*)d_in[16];
    const float* bc3   = (const float*)d_in[17];
    const float* Wc4   = (const float*)d_in[18];
    const float* bc4   = (const float*)d_in[19];
    const float* Wc5   = (const float*)d_in[20];
    const float* bc5   = (const float*)d_in[21];
    const float* Wo    = (const float*)d_in[22];
    const float* bo    = (const float*)d_in[23];
    float* out = (float*)d_out;

    cudaFuncSetAttribute(k_recur_mma, cudaFuncAttributeMaxDynamicSharedMemorySize,
                         MSM_BYTES);
    cudaFuncSetAttribute(k_recur_mma3, cudaFuncAttributeMaxDynamicSharedMemorySize,
                         M3_BYTES);
    cudaFuncSetAttribute(k_bgemm, cudaFuncAttributeMaxDynamicSharedMemorySize,
                         BSM_BYTES);
    cudaFuncSetAttribute(k_bgemm3, cudaFuncAttributeMaxDynamicSharedMemorySize,
                         BSM3_BYTES);

    float *pGi, *pS0, *pU;
    int* pNsel;
    __nv_bfloat16 *pAh, *pAl, *pWh, *pWl, *pW3;
    cudaGetSymbolAddress((void**)&pGi,   g_Gi);
    cudaGetSymbolAddress((void**)&pS0,   g_seq0);
    cudaGetSymbolAddress((void**)&pU,    g_U);
    cudaGetSymbolAddress((void**)&pNsel, g_nsel);
    cudaGetSymbolAddress((void**)&pAh,   g_Ah);
    cudaGetSymbolAddress((void**)&pAl,   g_Al);
    cudaGetSymbolAddress((void**)&pWh,   g_Wh);
    cudaGetSymbolAddress((void**)&pWl,   g_Wl);
    cudaGetSymbolAddress((void**)&pW3,   g_W3);

    // ---- selector GRU: 3-plane/6-term; A split fused into the GEMM ----
    k_split3<<<(G3*EE + 255)/256, 256>>>(Wih_c, pWh, pWl, pW3, (size_t)G3*EE);
    k_bgemm3<<<dim3(G3/128, MALL/128), 256, BSM3_BYTES>>>(
        pGi, emb, pWh, pWl, pW3, bih_c, MALL, G3, EE);
    k_split3<<<(G3*HH + 255)/256, 256>>>(Whh_c, pWh, pWl, pW3, (size_t)G3*HH);
    k_recur_mma3<<<NBLK, 512, M3_BYTES>>>(pGi, pS0, pWh, pWl, pW3, bhh_c);
    k_selargmax<<<(BB*TT*32 + 255)/256, 256>>>(pS0, Ws, bs);
    k_fix<<<BB, 32>>>(mask);
    k_gather<<<MALL, EE/4>>>(emb, pAh, pAl);

    // ---- layer 0 ----
    k_split<<<(G3*EE + 255)/256, 256>>>(Wih0, pWh, pWl, (size_t)G3*EE);
    k_bgemm<<<dim3(G3/128, MALL/128), 256, BSM_BYTES>>>(
        pGi, pAh, pAl, pWh, pWl, bih0, MALL, G3, EE, pNsel, 1);
    k_split<<<(G3*HH + 255)/256, 256>>>(Whh0, pWh, pWl, (size_t)G3*HH);
    k_recur_mma<<<NBLK, 512, MSM_BYTES>>>(pGi, pAh, pAl, pWh, pWl, bhh0, pNsel);

    // ---- layer 1 ----
    k_split<<<(G3*HH + 255)/256, 256>>>(Wih1, pWh, pWl, (size_t)G3*HH);
    k_bgemm<<<dim3(G3/128, MALL/128), 256, BSM_BYTES>>>(
        pGi, pAh, pAl, pWh, pWl, bih1, MALL, G3, HH, pNsel, 1);
    k_split<<<(G3*HH + 255)/256, 256>>>(Whh1, pWh, pWl, (size_t)G3*HH);
    k_recur_mma<<<NBLK, 512, MSM_BYTES>>>(pGi, pAh, pAl, pWh, pWl, bhh1, pNsel);

    // ---- convs: ONE combined bgemm (N=3072) over concatenated weights ----
    k_zero_pooled<<<(BB*3*NF + 255)/256, 256>>>();
    k_split<<<(NF*3*HH + 255)/256, 256>>>(Wc3, pWh, pWl, (size_t)NF*3*HH);
    k_split<<<(NF*4*HH + 255)/256, 256>>>(Wc4, pWh + (size_t)NF*3*HH,
                                          pWl + (size_t)NF*3*HH, (size_t)NF*4*HH);
    k_split<<<(NF*5*HH + 255)/256, 256>>>(Wc5, pWh + (size_t)NF*7*HH,
                                          pWl + (size_t)NF*7*HH, (size_t)NF*5*HH);
    k_bgemm<<<dim3(NCV/128, MALL/128), 256, BSM_BYTES>>>(
        pU, pAh, pAl, pWh, pWl, nullptr, MALL, NCV, HH, pNsel, 1);
    k_pool<<<dim3(BB, 8), NF>>>(pU, bc3, 3, 0,    0);
    k_pool<<<dim3(BB, 8), NF>>>(pU, bc4, 4, NF*3, NF);
    k_pool<<<dim3(BB, 8), NF>>>(pU, bc5, 5, NF*7, 2*NF);

    // ---- final projection ----
    k_final<<<BB, 256>>>(Wo, bo, out);
}